// round 1
// baseline (speedup 1.0000x reference)
#include <cuda_runtime.h>
#include <math_constants.h>

#define B_   2
#define S_   2048
#define H_   768
#define NH_  12
#define HD_  64
#define ROWS (B_*S_)          // 4096

// ---------------- scratch (no allocations allowed) ----------------
__device__ float g_xn[ROWS*H_];
__device__ float g_q [ROWS*H_];
__device__ float g_k [ROWS*H_];
__device__ float g_v [ROWS*H_];
__device__ float g_ao[ROWS*H_];

// ---------------- LayerNorm: one block per row ----------------
__global__ void ln_kernel(const float* __restrict__ x, const float* __restrict__ gam,
                          const float* __restrict__ bet, float* __restrict__ o)
{
    int row = blockIdx.x;
    int t = threadIdx.x;                    // 256 threads, 3 elems each
    const float* xr = x + (size_t)row * H_;
    float v0 = xr[t], v1 = xr[t+256], v2 = xr[t+512];
    float s  = v0 + v1 + v2;
    float sq = v0*v0 + v1*v1 + v2*v2;
    #pragma unroll
    for (int off = 16; off; off >>= 1) {
        s  += __shfl_xor_sync(~0u, s,  off);
        sq += __shfl_xor_sync(~0u, sq, off);
    }
    __shared__ float rs[8], rq[8];
    int w = t >> 5;
    if ((t & 31) == 0) { rs[w] = s; rq[w] = sq; }
    __syncthreads();
    if (t < 32) {
        float a  = (t < 8) ? rs[t] : 0.f;
        float b2 = (t < 8) ? rq[t] : 0.f;
        #pragma unroll
        for (int off = 4; off; off >>= 1) {
            a  += __shfl_xor_sync(~0u, a,  off);
            b2 += __shfl_xor_sync(~0u, b2, off);
        }
        if (t == 0) { rs[0] = a; rq[0] = b2; }
    }
    __syncthreads();
    float mu  = rs[0] * (1.f / H_);
    float var = rq[0] * (1.f / H_) - mu * mu;
    float r   = rsqrtf(var + 1e-5f);
    float* orow = o + (size_t)row * H_;
    orow[t]     = (v0 - mu) * r * gam[t]     + bet[t];
    orow[t+256] = (v1 - mu) * r * gam[t+256] + bet[t+256];
    orow[t+512] = (v2 - mu) * r * gam[t+512] + bet[t+512];
}

// ---------------- SGEMM: [4096 x 768] @ [768 x 768], BM=BN=64, BK=16 ----------------
// mode 0: C = A@W + bias                           (Q)
// mode 1: C = A@W + bias + 0.5*memadd              (K, V)
// mode 2: C = ((A@W + bias)*gate + gbias) * dyn[m] (output proj)
__global__ void __launch_bounds__(256) gemm768(
    const float* __restrict__ A, const float* __restrict__ W,
    const float* __restrict__ bias, const float* __restrict__ memadd,
    const float* __restrict__ gate, const float* __restrict__ gbias,
    const float* __restrict__ dyn, float* __restrict__ C, int mode)
{
    __shared__ float As[16][65];   // [k][m], padded
    __shared__ float Ws[16][64];   // [k][n]
    int t  = threadIdx.x;
    int tx = t & 15, ty = t >> 4;
    int m0 = blockIdx.x * 64, n0 = blockIdx.y * 64;
    float acc[4][4] = {};

    int arow = t >> 2,  ak = (t & 3)  * 4;   // A loader: 64 rows x 16 k
    int wk   = t >> 4,  wn = (t & 15) * 4;   // W loader: 16 k   x 64 n
    const float* Ap = A + (size_t)(m0 + arow) * H_ + ak;
    const float* Wp = W + (size_t)wk * H_ + n0 + wn;

    for (int k0 = 0; k0 < H_; k0 += 16) {
        float4 av = *(const float4*)(Ap + k0);
        float4 wv = *(const float4*)(Wp + (size_t)k0 * H_);
        As[ak+0][arow] = av.x; As[ak+1][arow] = av.y;
        As[ak+2][arow] = av.z; As[ak+3][arow] = av.w;
        *(float4*)&Ws[wk][wn] = wv;
        __syncthreads();
        #pragma unroll
        for (int kk = 0; kk < 16; kk++) {
            float a0 = As[kk][ty*4+0], a1 = As[kk][ty*4+1];
            float a2 = As[kk][ty*4+2], a3 = As[kk][ty*4+3];
            float4 b = *(const float4*)&Ws[kk][tx*4];
            acc[0][0] += a0*b.x; acc[0][1] += a0*b.y; acc[0][2] += a0*b.z; acc[0][3] += a0*b.w;
            acc[1][0] += a1*b.x; acc[1][1] += a1*b.y; acc[1][2] += a1*b.z; acc[1][3] += a1*b.w;
            acc[2][0] += a2*b.x; acc[2][1] += a2*b.y; acc[2][2] += a2*b.z; acc[2][3] += a2*b.w;
            acc[3][0] += a3*b.x; acc[3][1] += a3*b.y; acc[3][2] += a3*b.z; acc[3][3] += a3*b.w;
        }
        __syncthreads();
    }

    int n = n0 + tx * 4;
    float4 bv = *(const float4*)(bias + n);
    float g = 1.f, gb = 0.f;
    if (mode == 2) { g = gate[0]; gb = gbias[0]; }
    #pragma unroll
    for (int i = 0; i < 4; i++) {
        int m = m0 + ty * 4 + i;
        float4 o;
        o.x = acc[i][0] + bv.x; o.y = acc[i][1] + bv.y;
        o.z = acc[i][2] + bv.z; o.w = acc[i][3] + bv.w;
        if (mode == 1) {
            float4 mv = *(const float4*)(memadd + (size_t)m * H_ + n);
            o.x += 0.5f*mv.x; o.y += 0.5f*mv.y; o.z += 0.5f*mv.z; o.w += 0.5f*mv.w;
        } else if (mode == 2) {
            float d = dyn[m];
            o.x = (o.x*g + gb)*d; o.y = (o.y*g + gb)*d;
            o.z = (o.z*g + gb)*d; o.w = (o.w*g + gb)*d;
        }
        *(float4*)(C + (size_t)m * H_ + n) = o;
    }
}

// ---------------- Flash attention: BM=BN=64, HD=64, fp32, online softmax ----------------
#define FPAD 68
__global__ void __launch_bounds__(256) flash_kernel(
    const float* __restrict__ q, const float* __restrict__ k,
    const float* __restrict__ v, const int* __restrict__ mask,
    float* __restrict__ o)
{
    extern __shared__ float sm[];
    float* Qs = sm;                  // [64][FPAD]  row=query, col=d
    float* KP = sm + 64*FPAD;        // Kts[d][nn]  then aliased as Ps[mm][nn]
    float* Vs = sm + 2*64*FPAD;      // [nn][c]
    int t  = threadIdx.x;
    int tx = t & 15, ty = t >> 4;
    int q0 = blockIdx.x * 64;
    int h  = blockIdx.y;
    int b  = blockIdx.z;
    const size_t base = ((size_t)b * S_) * H_ + (size_t)h * HD_;

    for (int i = t; i < 64*16; i += 256) {
        int r = i >> 4, c4 = (i & 15) * 4;
        float4 val = *(const float4*)(q + base + (size_t)(q0 + r) * H_ + c4);
        *(float4*)&Qs[r*FPAD + c4] = val;
    }

    float m_i[4], l_i[4], acc[4][4];
    #pragma unroll
    for (int i = 0; i < 4; i++) {
        m_i[i] = -CUDART_INF_F; l_i[i] = 0.f;
        acc[i][0] = acc[i][1] = acc[i][2] = acc[i][3] = 0.f;
    }

    const int* mb = mask + (size_t)b * S_ * S_;

    for (int k0 = 0; k0 < S_; k0 += 64) {
        // load K (transposed: [d][nn]) and V ([nn][c])
        for (int i = t; i < 64*16; i += 256) {
            int r = i >> 4, c4 = (i & 15) * 4;
            float4 kv = *(const float4*)(k + base + (size_t)(k0 + r) * H_ + c4);
            KP[(c4+0)*FPAD + r] = kv.x;
            KP[(c4+1)*FPAD + r] = kv.y;
            KP[(c4+2)*FPAD + r] = kv.z;
            KP[(c4+3)*FPAD + r] = kv.w;
            float4 vv = *(const float4*)(v + base + (size_t)(k0 + r) * H_ + c4);
            *(float4*)&Vs[r*FPAD + c4] = vv;
        }
        __syncthreads();

        // S = Q K^T
        float s[4][4];
        #pragma unroll
        for (int i = 0; i < 4; i++)
            s[i][0] = s[i][1] = s[i][2] = s[i][3] = 0.f;
        #pragma unroll 16
        for (int d = 0; d < 64; d++) {
            float4 bvec = *(const float4*)&KP[d*FPAD + tx*4];
            float a0 = Qs[(ty*4+0)*FPAD + d];
            float a1 = Qs[(ty*4+1)*FPAD + d];
            float a2 = Qs[(ty*4+2)*FPAD + d];
            float a3 = Qs[(ty*4+3)*FPAD + d];
            s[0][0] += a0*bvec.x; s[0][1] += a0*bvec.y; s[0][2] += a0*bvec.z; s[0][3] += a0*bvec.w;
            s[1][0] += a1*bvec.x; s[1][1] += a1*bvec.y; s[1][2] += a1*bvec.z; s[1][3] += a1*bvec.w;
            s[2][0] += a2*bvec.x; s[2][1] += a2*bvec.y; s[2][2] += a2*bvec.z; s[2][3] += a2*bvec.w;
            s[3][0] += a3*bvec.x; s[3][1] += a3*bvec.y; s[3][2] += a3*bvec.z; s[3][3] += a3*bvec.w;
        }

        // mask + scale + online softmax (rows split across 16 lanes of a half-warp)
        #pragma unroll
        for (int i = 0; i < 4; i++) {
            int qi = q0 + ty*4 + i;
            int4 mv = *(const int4*)(mb + (size_t)qi * S_ + k0 + tx*4);
            s[i][0] = mv.x ? s[i][0] * 0.125f : -CUDART_INF_F;
            s[i][1] = mv.y ? s[i][1] * 0.125f : -CUDART_INF_F;
            s[i][2] = mv.z ? s[i][2] * 0.125f : -CUDART_INF_F;
            s[i][3] = mv.w ? s[i][3] * 0.125f : -CUDART_INF_F;
            float mx = fmaxf(fmaxf(s[i][0], s[i][1]), fmaxf(s[i][2], s[i][3]));
            #pragma unroll
            for (int off = 8; off; off >>= 1)
                mx = fmaxf(mx, __shfl_xor_sync(~0u, mx, off));
            float nm = fmaxf(m_i[i], mx);
            float p0 = __expf(s[i][0]-nm), p1 = __expf(s[i][1]-nm);
            float p2 = __expf(s[i][2]-nm), p3 = __expf(s[i][3]-nm);
            float rs2 = p0 + p1 + p2 + p3;
            #pragma unroll
            for (int off = 8; off; off >>= 1)
                rs2 += __shfl_xor_sync(~0u, rs2, off);
            float corr = __expf(m_i[i] - nm);
            m_i[i] = nm;
            l_i[i] = l_i[i]*corr + rs2;
            acc[i][0] *= corr; acc[i][1] *= corr; acc[i][2] *= corr; acc[i][3] *= corr;
            s[i][0] = p0; s[i][1] = p1; s[i][2] = p2; s[i][3] = p3;
        }
        __syncthreads();                       // done reading KP as K
        #pragma unroll
        for (int i = 0; i < 4; i++)
            *(float4*)&KP[(ty*4+i)*FPAD + tx*4] =
                make_float4(s[i][0], s[i][1], s[i][2], s[i][3]);
        __syncthreads();                       // Ps visible

        // O += P @ V
        #pragma unroll 16
        for (int nn = 0; nn < 64; nn++) {
            float4 bvec = *(const float4*)&Vs[nn*FPAD + tx*4];
            float a0 = KP[(ty*4+0)*FPAD + nn];
            float a1 = KP[(ty*4+1)*FPAD + nn];
            float a2 = KP[(ty*4+2)*FPAD + nn];
            float a3 = KP[(ty*4+3)*FPAD + nn];
            acc[0][0] += a0*bvec.x; acc[0][1] += a0*bvec.y; acc[0][2] += a0*bvec.z; acc[0][3] += a0*bvec.w;
            acc[1][0] += a1*bvec.x; acc[1][1] += a1*bvec.y; acc[1][2] += a1*bvec.z; acc[1][3] += a1*bvec.w;
            acc[2][0] += a2*bvec.x; acc[2][1] += a2*bvec.y; acc[2][2] += a2*bvec.z; acc[2][3] += a2*bvec.w;
            acc[3][0] += a3*bvec.x; acc[3][1] += a3*bvec.y; acc[3][2] += a3*bvec.z; acc[3][3] += a3*bvec.w;
        }
        __syncthreads();                       // done reading KP/Vs before next tile load
    }

    #pragma unroll
    for (int i = 0; i < 4; i++) {
        float inv = 1.f / l_i[i];
        float4 ov = make_float4(acc[i][0]*inv, acc[i][1]*inv, acc[i][2]*inv, acc[i][3]*inv);
        *(float4*)(o + base + (size_t)(q0 + ty*4 + i) * H_ + tx*4) = ov;
    }
}

// ---------------- launch ----------------
extern "C" void kernel_launch(void* const* d_in, const int* in_sizes, int n_in,
                              void* d_out, int out_size)
{
    const float* hidden = (const float*)d_in[0];
    const float* cross  = (const float*)d_in[1];
    const int*   amask  = (const int*)  d_in[2];
    const float* mem    = (const float*)d_in[3];   // [2,B,S,H]
    const float* dyn    = (const float*)d_in[4];   // [B,S,1]
    const float* Wq = (const float*)d_in[5];  const float* bq = (const float*)d_in[6];
    const float* Wk = (const float*)d_in[7];  const float* bk = (const float*)d_in[8];
    const float* Wv = (const float*)d_in[9];  const float* bv = (const float*)d_in[10];
    const float* Wo = (const float*)d_in[11]; const float* bo = (const float*)d_in[12];
    const float* gate  = (const float*)d_in[13];
    const float* gbias = (const float*)d_in[14];
    const float* lng   = (const float*)d_in[15];
    const float* lnb   = (const float*)d_in[16];
    float* out = (float*)d_out;

    float *xn, *q, *k, *v, *ao;
    cudaGetSymbolAddress((void**)&xn, g_xn);
    cudaGetSymbolAddress((void**)&q,  g_q);
    cudaGetSymbolAddress((void**)&k,  g_k);
    cudaGetSymbolAddress((void**)&v,  g_v);
    cudaGetSymbolAddress((void**)&ao, g_ao);

    ln_kernel<<<ROWS, 256>>>(hidden, lng, lnb, xn);

    dim3 gg(64, 12);   // 4096/64 x 768/64
    gemm768<<<gg, 256>>>(xn,    Wq, bq, nullptr,               nullptr, nullptr, nullptr, q,   0);
    gemm768<<<gg, 256>>>(cross, Wk, bk, mem,                   nullptr, nullptr, nullptr, k,   1);
    gemm768<<<gg, 256>>>(cross, Wv, bv, mem + (size_t)ROWS*H_, nullptr, nullptr, nullptr, v,   1);

    int smem = 3 * 64 * FPAD * (int)sizeof(float);   // 52224 bytes
    cudaFuncSetAttribute(flash_kernel, cudaFuncAttributeMaxDynamicSharedMemorySize, smem);
    flash_kernel<<<dim3(S_/64, NH_, B_), 256, smem>>>(q, k, v, amask, ao);

    gemm768<<<gg, 256>>>(ao, Wo, bo, nullptr, gate, gbias, dyn, out, 2);
}

// round 2
// speedup vs baseline: 2.2692x; 2.2692x over previous
#include <cuda_runtime.h>
#include <cuda_bf16.h>
#include <math_constants.h>

#define B_   2
#define S_   2048
#define H_   768
#define NH_  12
#define HD_  64
#define ROWS (B_*S_)          // 4096

// ---------------- scratch (bf16 hi/lo split operands) ----------------
__device__ __nv_bfloat16 g_xn_hi[ROWS*H_], g_xn_lo[ROWS*H_];
__device__ __nv_bfloat16 g_cr_hi[ROWS*H_], g_cr_lo[ROWS*H_];
__device__ __nv_bfloat16 g_q_hi [ROWS*H_], g_q_lo [ROWS*H_];
__device__ __nv_bfloat16 g_k_hi [ROWS*H_], g_k_lo [ROWS*H_];
__device__ __nv_bfloat16 g_v_hi [ROWS*H_], g_v_lo [ROWS*H_];
__device__ __nv_bfloat16 g_ao_hi[ROWS*H_], g_ao_lo[ROWS*H_];
__device__ __nv_bfloat16 g_wt_hi[4*H_*H_], g_wt_lo[4*H_*H_];   // W^T [n][k]

// ---------------- helpers ----------------
__device__ __forceinline__ unsigned sa(const void* p) {
    return (unsigned)__cvta_generic_to_shared(p);
}
__device__ __forceinline__ void ldsm4(unsigned r[4], unsigned addr) {
    asm volatile("ldmatrix.sync.aligned.m8n8.x4.shared.b16 {%0,%1,%2,%3}, [%4];"
        : "=r"(r[0]), "=r"(r[1]), "=r"(r[2]), "=r"(r[3]) : "r"(addr));
}
__device__ __forceinline__ void ldsm4t(unsigned r[4], unsigned addr) {
    asm volatile("ldmatrix.sync.aligned.m8n8.x4.trans.shared.b16 {%0,%1,%2,%3}, [%4];"
        : "=r"(r[0]), "=r"(r[1]), "=r"(r[2]), "=r"(r[3]) : "r"(addr));
}
__device__ __forceinline__ void mma_bf16(float d[4], const unsigned a[4],
                                         unsigned b0, unsigned b1) {
    asm volatile("mma.sync.aligned.m16n8k16.row.col.f32.bf16.bf16.f32 "
        "{%0,%1,%2,%3}, {%4,%5,%6,%7}, {%8,%9}, {%0,%1,%2,%3};"
        : "+f"(d[0]), "+f"(d[1]), "+f"(d[2]), "+f"(d[3])
        : "r"(a[0]), "r"(a[1]), "r"(a[2]), "r"(a[3]), "r"(b0), "r"(b1));
}
__device__ __forceinline__ unsigned packbf(float lo, float hi) {
    unsigned r;
    asm("cvt.rn.bf16x2.f32 %0, %1, %2;" : "=r"(r) : "f"(hi), "f"(lo));
    return r;
}
__device__ __forceinline__ void splitf(float x, float& h, float& l) {
    __nv_bfloat16 bh = __float2bfloat16_rn(x);
    h = __bfloat162float(bh);
    l = x - h;
}

// ---------------- weight prep: transpose + split ----------------
__global__ void wprep(const float* __restrict__ W,
                      __nv_bfloat16* __restrict__ Th, __nv_bfloat16* __restrict__ Tl)
{
    __shared__ float tile[32][33];
    int k0 = blockIdx.x * 32, n0 = blockIdx.y * 32;
    int tx = threadIdx.x, ty = threadIdx.y;          // 32 x 8
    for (int i = ty; i < 32; i += 8)
        tile[i][tx] = W[(size_t)(k0 + i) * H_ + n0 + tx];
    __syncthreads();
    for (int i = ty; i < 32; i += 8) {
        float v = tile[tx][i];                       // W[k0+tx][n0+i]
        float h, l; splitf(v, h, l);
        size_t o = (size_t)(n0 + i) * H_ + k0 + tx;
        Th[o] = __float2bfloat16_rn(h);
        Tl[o] = __float2bfloat16_rn(l);
    }
}

// ---------------- elementwise split (cross_states) ----------------
__global__ void splitconv(const float* __restrict__ x,
                          __nv_bfloat16* __restrict__ oh, __nv_bfloat16* __restrict__ ol)
{
    int idx = (blockIdx.x * 256 + threadIdx.x) * 4;
    float4 v = *(const float4*)(x + idx);
    float h0,l0,h1,l1,h2,l2,h3,l3;
    splitf(v.x,h0,l0); splitf(v.y,h1,l1); splitf(v.z,h2,l2); splitf(v.w,h3,l3);
    unsigned* ph = (unsigned*)(oh + idx);
    unsigned* pl = (unsigned*)(ol + idx);
    ph[0] = packbf(h0,h1); ph[1] = packbf(h2,h3);
    pl[0] = packbf(l0,l1); pl[1] = packbf(l2,l3);
}

// ---------------- LayerNorm -> split bf16 ----------------
__global__ void ln_kernel(const float* __restrict__ x, const float* __restrict__ gam,
                          const float* __restrict__ bet,
                          __nv_bfloat16* __restrict__ oh, __nv_bfloat16* __restrict__ ol)
{
    int row = blockIdx.x;
    int t = threadIdx.x;                    // 256 threads, 3 elems each
    const float* xr = x + (size_t)row * H_;
    float v0 = xr[t], v1 = xr[t+256], v2 = xr[t+512];
    float s  = v0 + v1 + v2;
    float sq = v0*v0 + v1*v1 + v2*v2;
    #pragma unroll
    for (int off = 16; off; off >>= 1) {
        s  += __shfl_xor_sync(~0u, s,  off);
        sq += __shfl_xor_sync(~0u, sq, off);
    }
    __shared__ float rs[8], rq[8];
    int w = t >> 5;
    if ((t & 31) == 0) { rs[w] = s; rq[w] = sq; }
    __syncthreads();
    if (t < 32) {
        float a  = (t < 8) ? rs[t] : 0.f;
        float b2 = (t < 8) ? rq[t] : 0.f;
        #pragma unroll
        for (int off = 4; off; off >>= 1) {
            a  += __shfl_xor_sync(~0u, a,  off);
            b2 += __shfl_xor_sync(~0u, b2, off);
        }
        if (t == 0) { rs[0] = a; rq[0] = b2; }
    }
    __syncthreads();
    float mu  = rs[0] * (1.f / H_);
    float var = rq[0] * (1.f / H_) - mu * mu;
    float r   = rsqrtf(var + 1e-5f);
    size_t base = (size_t)row * H_;
    #pragma unroll
    for (int e = 0; e < 3; e++) {
        int c = t + e * 256;
        float val = ((e==0?v0:e==1?v1:v2) - mu) * r * gam[c] + bet[c];
        float h, l; splitf(val, h, l);
        oh[base + c] = __float2bfloat16_rn(h);
        ol[base + c] = __float2bfloat16_rn(l);
    }
}

// ---------------- GEMM: [4096xH] @ W -> C, bf16-split mma ----------------
// mode 0: C = A@W + bias            -> Chi/Clo
// mode 1: C = A@W + bias + 0.5*mem  -> Chi/Clo
// mode 2: C = ((A@W + bias)*g + gb)*dyn[m] -> Cf (fp32)
#define GP 40
__global__ void __launch_bounds__(256) gemm_mma(
    const __nv_bfloat16* __restrict__ Ahi, const __nv_bfloat16* __restrict__ Alo,
    const __nv_bfloat16* __restrict__ Bhi, const __nv_bfloat16* __restrict__ Blo,
    const float* __restrict__ bias, const float* __restrict__ memadd,
    const float* __restrict__ gate, const float* __restrict__ gbias,
    const float* __restrict__ dyn,
    __nv_bfloat16* __restrict__ Chi, __nv_bfloat16* __restrict__ Clo,
    float* __restrict__ Cf, int mode)
{
    __shared__ __nv_bfloat16 As[2][128][GP];
    __shared__ __nv_bfloat16 Bs[2][128][GP];
    int t = threadIdx.x, w = t >> 5, lane = t & 31;
    int wm = w & 1, wn = w >> 1;
    int m0 = blockIdx.x * 128, n0 = blockIdx.y * 128;
    int g = lane >> 2, qd = lane & 3;

    float acc[4][4][4] = {};

    uint4 rah[2], ral[2], rbh[2], rbl[2];
    int lrow[2], lcol[2];
    #pragma unroll
    for (int i = 0; i < 2; i++) {
        int c = t + i * 256;
        lrow[i] = c >> 2; lcol[i] = (c & 3) * 8;
    }
    auto fetch = [&](int k0) {
        #pragma unroll
        for (int i = 0; i < 2; i++) {
            size_t ai = (size_t)(m0 + lrow[i]) * H_ + k0 + lcol[i];
            rah[i] = *(const uint4*)(Ahi + ai);
            ral[i] = *(const uint4*)(Alo + ai);
            size_t bi = (size_t)(n0 + lrow[i]) * H_ + k0 + lcol[i];
            rbh[i] = *(const uint4*)(Bhi + bi);
            rbl[i] = *(const uint4*)(Blo + bi);
        }
    };

    int lr = lane & 15, lc = (lane >> 4) * 8;
    unsigned aH = sa(&As[0][wm*64 + lr][lc]);
    unsigned aL = sa(&As[1][wm*64 + lr][lc]);
    unsigned bH = sa(&Bs[0][wn*32 + lr][lc]);
    unsigned bL = sa(&Bs[1][wn*32 + lr][lc]);

    fetch(0);
    for (int it = 0; it < H_/32; it++) {
        __syncthreads();
        #pragma unroll
        for (int i = 0; i < 2; i++) {
            *(uint4*)&As[0][lrow[i]][lcol[i]] = rah[i];
            *(uint4*)&As[1][lrow[i]][lcol[i]] = ral[i];
            *(uint4*)&Bs[0][lrow[i]][lcol[i]] = rbh[i];
            *(uint4*)&Bs[1][lrow[i]][lcol[i]] = rbl[i];
        }
        __syncthreads();
        if (it < H_/32 - 1) fetch((it + 1) * 32);

        #pragma unroll
        for (int kh = 0; kh < 2; kh++) {
            unsigned ah[4][4], al[4][4], bh[2][4], bl[2][4];
            #pragma unroll
            for (int mt = 0; mt < 4; mt++) {
                unsigned off = (mt*16*GP + kh*16) * 2;
                ldsm4(ah[mt], aH + off);
                ldsm4(al[mt], aL + off);
            }
            #pragma unroll
            for (int ng = 0; ng < 2; ng++) {
                unsigned off = (ng*16*GP + kh*16) * 2;
                ldsm4(bh[ng], bH + off);
                ldsm4(bl[ng], bL + off);
            }
            #pragma unroll
            for (int mt = 0; mt < 4; mt++)
                #pragma unroll
                for (int ng = 0; ng < 2; ng++)
                    #pragma unroll
                    for (int tl = 0; tl < 2; tl++) {
                        float* d = acc[mt][ng*2 + tl];
                        mma_bf16(d, ah[mt], bh[ng][tl], bh[ng][tl+2]);
                        mma_bf16(d, ah[mt], bl[ng][tl], bl[ng][tl+2]);
                        mma_bf16(d, al[mt], bh[ng][tl], bh[ng][tl+2]);
                    }
        }
    }

    float gv = 1.f, gb = 0.f;
    if (mode == 2) { gv = gate[0]; gb = gbias[0]; }
    #pragma unroll
    for (int mt = 0; mt < 4; mt++) {
        #pragma unroll
        for (int nt = 0; nt < 4; nt++) {
            int col = n0 + wn*32 + nt*8 + qd*2;
            float2 bv = *(const float2*)(bias + col);
            #pragma unroll
            for (int rj = 0; rj < 2; rj++) {
                int row = m0 + wm*64 + mt*16 + g + rj*8;
                float x0 = acc[mt][nt][rj*2]   + bv.x;
                float x1 = acc[mt][nt][rj*2+1] + bv.y;
                if (mode == 1) {
                    float2 mm = *(const float2*)(memadd + (size_t)row * H_ + col);
                    x0 += 0.5f * mm.x; x1 += 0.5f * mm.y;
                }
                if (mode == 2) {
                    float d = dyn[row];
                    x0 = (x0*gv + gb) * d; x1 = (x1*gv + gb) * d;
                    *(float2*)(Cf + (size_t)row * H_ + col) = make_float2(x0, x1);
                } else {
                    float h0,l0,h1,l1;
                    splitf(x0,h0,l0); splitf(x1,h1,l1);
                    size_t o = (size_t)row * H_ + col;
                    *(unsigned*)(Chi + o) = packbf(h0,h1);
                    *(unsigned*)(Clo + o) = packbf(l0,l1);
                }
            }
        }
    }
}

// ---------------- Flash attention, bf16-split mma ----------------
#define FP 72
#define MP 68
__global__ void __launch_bounds__(128) flash_mma(
    const __nv_bfloat16* __restrict__ qh, const __nv_bfloat16* __restrict__ ql,
    const __nv_bfloat16* __restrict__ kh, const __nv_bfloat16* __restrict__ kl,
    const __nv_bfloat16* __restrict__ vh, const __nv_bfloat16* __restrict__ vl,
    const int* __restrict__ mask,
    __nv_bfloat16* __restrict__ aoh, __nv_bfloat16* __restrict__ aol)
{
    extern __shared__ char fsm[];
    __nv_bfloat16* Qh = (__nv_bfloat16*)fsm;
    __nv_bfloat16* Ql = Qh + 64*FP;
    __nv_bfloat16* Kh = Ql + 64*FP;
    __nv_bfloat16* Kl = Kh + 64*FP;
    __nv_bfloat16* Vh = Kl + 64*FP;
    __nv_bfloat16* Vl = Vh + 64*FP;
    unsigned char* Ms = (unsigned char*)(Vl + 64*FP);

    int t = threadIdx.x, w = t >> 5, lane = t & 31;
    int g = lane >> 2, qd = lane & 3;
    int q0 = blockIdx.x * 64, h = blockIdx.y, b = blockIdx.z;
    const size_t basec = (size_t)b * S_ * H_ + h * 64;

    // load Q
    for (int i = t; i < 512; i += 128) {
        int r = i >> 3, c = (i & 7) * 8;
        size_t gi = basec + (size_t)(q0 + r) * H_ + c;
        *(uint4*)&Qh[r*FP + c] = *(const uint4*)(qh + gi);
        *(uint4*)&Ql[r*FP + c] = *(const uint4*)(ql + gi);
    }
    __syncthreads();

    int lr = lane & 15, lc = (lane >> 4) * 8;
    unsigned qfh[4][4], qfl[4][4];
    #pragma unroll
    for (int kb = 0; kb < 4; kb++) {
        ldsm4(qfh[kb], sa(&Qh[(w*16 + lr)*FP + lc + kb*16]));
        ldsm4(qfl[kb], sa(&Ql[(w*16 + lr)*FP + lc + kb*16]));
    }

    float mrow[2] = {-CUDART_INF_F, -CUDART_INF_F};
    float lrow_[2] = {0.f, 0.f};
    float oacc[8][4] = {};
    const int* mb = mask + (size_t)b * S_ * S_;

    for (int k0 = 0; k0 < S_; k0 += 64) {
        for (int i = t; i < 512; i += 128) {
            int r = i >> 3, c = (i & 7) * 8;
            size_t gi = basec + (size_t)(k0 + r) * H_ + c;
            *(uint4*)&Kh[r*FP + c] = *(const uint4*)(kh + gi);
            *(uint4*)&Kl[r*FP + c] = *(const uint4*)(kl + gi);
            *(uint4*)&Vh[r*FP + c] = *(const uint4*)(vh + gi);
            *(uint4*)&Vl[r*FP + c] = *(const uint4*)(vl + gi);
        }
        for (int i = t; i < 1024; i += 128) {
            int r = i >> 4, c4 = (i & 15) * 4;
            int4 mv = *(const int4*)(mb + (size_t)(q0 + r) * S_ + k0 + c4);
            uchar4 u;
            u.x = mv.x != 0; u.y = mv.y != 0; u.z = mv.z != 0; u.w = mv.w != 0;
            *(uchar4*)&Ms[r*MP + c4] = u;
        }
        __syncthreads();

        // scores S = Q K^T (split)
        float s[8][4] = {};
        #pragma unroll
        for (int kb = 0; kb < 4; kb++) {
            #pragma unroll
            for (int ng = 0; ng < 4; ng++) {
                unsigned b4h[4], b4l[4];
                unsigned off = ((ng*16 + lr)*FP + lc + kb*16) * 2;
                ldsm4(b4h, sa(Kh) + off);
                ldsm4(b4l, sa(Kl) + off);
                #pragma unroll
                for (int tl = 0; tl < 2; tl++) {
                    float* d = s[ng*2 + tl];
                    mma_bf16(d, qfh[kb], b4h[tl], b4h[tl+2]);
                    mma_bf16(d, qfh[kb], b4l[tl], b4l[tl+2]);
                    mma_bf16(d, qfl[kb], b4h[tl], b4h[tl+2]);
                }
            }
        }

        // mask + scale
        #pragma unroll
        for (int nt = 0; nt < 8; nt++)
            #pragma unroll
            for (int j = 0; j < 4; j++) {
                int row = w*16 + g + (j >> 1) * 8;
                int col = nt*8 + qd*2 + (j & 1);
                s[nt][j] = Ms[row*MP + col] ? s[nt][j] * 0.125f : -CUDART_INF_F;
            }

        // online softmax (2 rows per thread)
        #pragma unroll
        for (int rj = 0; rj < 2; rj++) {
            float mx = -CUDART_INF_F;
            #pragma unroll
            for (int nt = 0; nt < 8; nt++)
                mx = fmaxf(mx, fmaxf(s[nt][rj*2], s[nt][rj*2+1]));
            mx = fmaxf(mx, __shfl_xor_sync(~0u, mx, 1));
            mx = fmaxf(mx, __shfl_xor_sync(~0u, mx, 2));
            float nm = fmaxf(mrow[rj], mx);
            float corr, rsum = 0.f;
            if (nm == -CUDART_INF_F) {
                corr = 1.f;
                #pragma unroll
                for (int nt = 0; nt < 8; nt++) { s[nt][rj*2] = 0.f; s[nt][rj*2+1] = 0.f; }
            } else {
                corr = __expf(mrow[rj] - nm);
                #pragma unroll
                for (int nt = 0; nt < 8; nt++) {
                    float p0 = __expf(s[nt][rj*2]   - nm);
                    float p1 = __expf(s[nt][rj*2+1] - nm);
                    s[nt][rj*2] = p0; s[nt][rj*2+1] = p1;
                    rsum += p0 + p1;
                }
            }
            rsum += __shfl_xor_sync(~0u, rsum, 1);
            rsum += __shfl_xor_sync(~0u, rsum, 2);
            mrow[rj] = nm;
            lrow_[rj] = lrow_[rj] * corr + rsum;
            #pragma unroll
            for (int nt = 0; nt < 8; nt++) {
                oacc[nt][rj*2]   *= corr;
                oacc[nt][rj*2+1] *= corr;
            }
        }

        // pack P into A fragments (split)
        unsigned pfh[4][4], pfl[4][4];
        #pragma unroll
        for (int kb = 0; kb < 4; kb++) {
            #pragma unroll
            for (int half = 0; half < 2; half++) {
                int nt = kb*2 + half;
                float h0,l0,h1,l1;
                splitf(s[nt][0], h0, l0); splitf(s[nt][1], h1, l1);
                pfh[kb][half*2]   = packbf(h0, h1);
                pfl[kb][half*2]   = packbf(l0, l1);
                splitf(s[nt][2], h0, l0); splitf(s[nt][3], h1, l1);
                pfh[kb][half*2+1] = packbf(h0, h1);
                pfl[kb][half*2+1] = packbf(l0, l1);
            }
        }
        // wait: fragment order must be {a0,a1,a2,a3} = {(g,c01)t0, (g+8,c01)t0, (g,c01)t1, (g+8,c01)t1}
        // pfh[kb] built as {t0 rows g, t0 rows g+8, t1 rows g, t1 rows g+8} -> need index swap:
        // built order: [0]=tile0 j01 (rows g), [1]=tile0 j23 (rows g+8), [2]=tile1 j01, [3]=tile1 j23
        // required:    a0=tile0 rows g, a1=tile0 rows g+8, a2=tile1 rows g, a3=tile1 rows g+8  -> matches!

        // O += P V (split)
        #pragma unroll
        for (int kb = 0; kb < 4; kb++) {
            #pragma unroll
            for (int ng = 0; ng < 4; ng++) {
                unsigned v4h[4], v4l[4];
                unsigned off = ((kb*16 + lr)*FP + ng*16 + lc) * 2;
                ldsm4t(v4h, sa(Vh) + off);
                ldsm4t(v4l, sa(Vl) + off);
                #pragma unroll
                for (int tl = 0; tl < 2; tl++) {
                    float* d = oacc[ng*2 + tl];
                    mma_bf16(d, pfh[kb], v4h[tl*2], v4h[tl*2+1]);
                    mma_bf16(d, pfh[kb], v4l[tl*2], v4l[tl*2+1]);
                    mma_bf16(d, pfl[kb], v4h[tl*2], v4h[tl*2+1]);
                }
            }
        }
        __syncthreads();
    }

    // epilogue
    #pragma unroll
    for (int rj = 0; rj < 2; rj++) {
        float inv = lrow_[rj] > 0.f ? 1.f / lrow_[rj] : 0.f;
        int row = q0 + w*16 + g + rj*8;
        #pragma unroll
        for (int nt = 0; nt < 8; nt++) {
            int col = nt*8 + qd*2;
            float x0 = oacc[nt][rj*2] * inv, x1 = oacc[nt][rj*2+1] * inv;
            float h0,l0,h1,l1;
            splitf(x0,h0,l0); splitf(x1,h1,l1);
            size_t o = basec + (size_t)row * H_ + col;
            *(unsigned*)(aoh + o) = packbf(h0,h1);
            *(unsigned*)(aol + o) = packbf(l0,l1);
        }
    }
}

// ---------------- launch ----------------
extern "C" void kernel_launch(void* const* d_in, const int* in_sizes, int n_in,
                              void* d_out, int out_size)
{
    const float* hidden = (const float*)d_in[0];
    const float* cross  = (const float*)d_in[1];
    const int*   amask  = (const int*)  d_in[2];
    const float* mem    = (const float*)d_in[3];
    const float* dyn    = (const float*)d_in[4];
    const float* Wq = (const float*)d_in[5];  const float* bq = (const float*)d_in[6];
    const float* Wk = (const float*)d_in[7];  const float* bk = (const float*)d_in[8];
    const float* Wv = (const float*)d_in[9];  const float* bv = (const float*)d_in[10];
    const float* Wo = (const float*)d_in[11]; const float* bo = (const float*)d_in[12];
    const float* gate  = (const float*)d_in[13];
    const float* gbias = (const float*)d_in[14];
    const float* lng   = (const float*)d_in[15];
    const float* lnb   = (const float*)d_in[16];
    float* out = (float*)d_out;

    __nv_bfloat16 *xnh,*xnl,*crh,*crl,*qhp,*qlp,*khp,*klp,*vhp,*vlp,*aoh,*aol,*wth,*wtl;
    cudaGetSymbolAddress((void**)&xnh, g_xn_hi); cudaGetSymbolAddress((void**)&xnl, g_xn_lo);
    cudaGetSymbolAddress((void**)&crh, g_cr_hi); cudaGetSymbolAddress((void**)&crl, g_cr_lo);
    cudaGetSymbolAddress((void**)&qhp, g_q_hi);  cudaGetSymbolAddress((void**)&qlp, g_q_lo);
    cudaGetSymbolAddress((void**)&khp, g_k_hi);  cudaGetSymbolAddress((void**)&klp, g_k_lo);
    cudaGetSymbolAddress((void**)&vhp, g_v_hi);  cudaGetSymbolAddress((void**)&vlp, g_v_lo);
    cudaGetSymbolAddress((void**)&aoh, g_ao_hi); cudaGetSymbolAddress((void**)&aol, g_ao_lo);
    cudaGetSymbolAddress((void**)&wth, g_wt_hi); cudaGetSymbolAddress((void**)&wtl, g_wt_lo);

    dim3 wg(H_/32, H_/32);
    wprep<<<wg, dim3(32,8)>>>(Wq, wth + 0*H_*H_, wtl + 0*H_*H_);
    wprep<<<wg, dim3(32,8)>>>(Wk, wth + 1*H_*H_, wtl + 1*H_*H_);
    wprep<<<wg, dim3(32,8)>>>(Wv, wth + 2*H_*H_, wtl + 2*H_*H_);
    wprep<<<wg, dim3(32,8)>>>(Wo, wth + 3*H_*H_, wtl + 3*H_*H_);

    ln_kernel<<<ROWS, 256>>>(hidden, lng, lnb, xnh, xnl);
    splitconv<<<ROWS*H_/1024, 256>>>(cross, crh, crl);

    dim3 gg(ROWS/128, H_/128);
    gemm_mma<<<gg, 256>>>(xnh, xnl, wth + 0*H_*H_, wtl + 0*H_*H_,
                          bq, nullptr, nullptr, nullptr, nullptr, qhp, qlp, nullptr, 0);
    gemm_mma<<<gg, 256>>>(crh, crl, wth + 1*H_*H_, wtl + 1*H_*H_,
                          bk, mem, nullptr, nullptr, nullptr, khp, klp, nullptr, 1);
    gemm_mma<<<gg, 256>>>(crh, crl, wth + 2*H_*H_, wtl + 2*H_*H_,
                          bv, mem + (size_t)ROWS*H_, nullptr, nullptr, nullptr, vhp, vlp, nullptr, 1);

    int smem = 6*64*FP*2 + 64*MP;   // 59648 bytes
    cudaFuncSetAttribute(flash_mma, cudaFuncAttributeMaxDynamicSharedMemorySize, smem);
    flash_mma<<<dim3(S_/64, NH_, B_), 128, smem>>>(qhp, qlp, khp, klp, vhp, vlp, amask, aoh, aol);

    gemm_mma<<<gg, 256>>>(aoh, aol, wth + 3*H_*H_, wtl + 3*H_*H_,
                          bo, nullptr, gate, gbias, dyn, nullptr, nullptr, out, 2);
}

// round 4
// speedup vs baseline: 2.2700x; 1.0003x over previous
#include <cuda_runtime.h>
#include <cuda_bf16.h>
#include <math_constants.h>
#include <cstdint>

#define B_   2
#define S_   2048
#define H_   768
#define NH_  12
#define HD_  64
#define ROWS (B_*S_)          // 4096

// ---------------- scratch (bf16 hi/lo split operands) ----------------
__device__ __align__(256) __nv_bfloat16 g_xn_hi[ROWS*H_];
__device__ __align__(256) __nv_bfloat16 g_xn_lo[ROWS*H_];
__device__ __align__(256) __nv_bfloat16 g_cr_hi[ROWS*H_];
__device__ __align__(256) __nv_bfloat16 g_cr_lo[ROWS*H_];
__device__ __align__(256) __nv_bfloat16 g_q_hi [ROWS*H_];
__device__ __align__(256) __nv_bfloat16 g_q_lo [ROWS*H_];
__device__ __align__(256) __nv_bfloat16 g_k_hi [ROWS*H_];
__device__ __align__(256) __nv_bfloat16 g_k_lo [ROWS*H_];
__device__ __align__(256) __nv_bfloat16 g_v_hi [ROWS*H_];
__device__ __align__(256) __nv_bfloat16 g_v_lo [ROWS*H_];
__device__ __align__(256) __nv_bfloat16 g_ao_hi[ROWS*H_];
__device__ __align__(256) __nv_bfloat16 g_ao_lo[ROWS*H_];
__device__ __align__(256) __nv_bfloat16 g_wt_hi[4*H_*H_];
__device__ __align__(256) __nv_bfloat16 g_wt_lo[4*H_*H_];

// ---------------- helpers ----------------
__device__ __forceinline__ unsigned sa(const void* p) {
    return (unsigned)__cvta_generic_to_shared(p);
}
__device__ __forceinline__ void ldsm4(unsigned r[4], unsigned addr) {
    asm volatile("ldmatrix.sync.aligned.m8n8.x4.shared.b16 {%0,%1,%2,%3}, [%4];"
        : "=r"(r[0]), "=r"(r[1]), "=r"(r[2]), "=r"(r[3]) : "r"(addr));
}
__device__ __forceinline__ void ldsm4t(unsigned r[4], unsigned addr) {
    asm volatile("ldmatrix.sync.aligned.m8n8.x4.trans.shared.b16 {%0,%1,%2,%3}, [%4];"
        : "=r"(r[0]), "=r"(r[1]), "=r"(r[2]), "=r"(r[3]) : "r"(addr));
}
__device__ __forceinline__ void mma_bf16(float d[4], const unsigned a[4],
                                         unsigned b0, unsigned b1) {
    asm volatile("mma.sync.aligned.m16n8k16.row.col.f32.bf16.bf16.f32 "
        "{%0,%1,%2,%3}, {%4,%5,%6,%7}, {%8,%9}, {%0,%1,%2,%3};"
        : "+f"(d[0]), "+f"(d[1]), "+f"(d[2]), "+f"(d[3])
        : "r"(a[0]), "r"(a[1]), "r"(a[2]), "r"(a[3]), "r"(b0), "r"(b1));
}
__device__ __forceinline__ unsigned packbf(float lo, float hi) {
    unsigned r;
    asm("cvt.rn.bf16x2.f32 %0, %1, %2;" : "=r"(r) : "f"(hi), "f"(lo));
    return r;
}
__device__ __forceinline__ void splitf(float x, float& h, float& l) {
    __nv_bfloat16 bh = __float2bfloat16_rn(x);
    h = __bfloat162float(bh);
    l = x - h;
}
#define CP16(saddr, gptr) \
    asm volatile("cp.async.cg.shared.global [%0], [%1], 16;" :: "r"(saddr), "l"(gptr))
#define CP_COMMIT() asm volatile("cp.async.commit_group;" ::: "memory")
#define CP_WAIT0() asm volatile("cp.async.wait_group 0;" ::: "memory")
#define CP_WAIT1() asm volatile("cp.async.wait_group 1;" ::: "memory")

// ---------------- weight prep: transpose + split (4 matrices, one launch) ----------------
__global__ void wprep4(const float* __restrict__ W0, const float* __restrict__ W1,
                       const float* __restrict__ W2, const float* __restrict__ W3,
                       __nv_bfloat16* __restrict__ Th, __nv_bfloat16* __restrict__ Tl)
{
    __shared__ float tile[32][33];
    int z = blockIdx.z;
    const float* W = z == 0 ? W0 : z == 1 ? W1 : z == 2 ? W2 : W3;
    __nv_bfloat16* th = Th + (size_t)z * H_ * H_;
    __nv_bfloat16* tl = Tl + (size_t)z * H_ * H_;
    int k0 = blockIdx.x * 32, n0 = blockIdx.y * 32;
    int tx = threadIdx.x, ty = threadIdx.y;          // 32 x 8
    for (int i = ty; i < 32; i += 8)
        tile[i][tx] = W[(size_t)(k0 + i) * H_ + n0 + tx];
    __syncthreads();
    for (int i = ty; i < 32; i += 8) {
        float v = tile[tx][i];
        float h, l; splitf(v, h, l);
        size_t o = (size_t)(n0 + i) * H_ + k0 + tx;
        th[o] = __float2bfloat16_rn(h);
        tl[o] = __float2bfloat16_rn(l);
    }
}

// ---------------- elementwise split (cross_states) ----------------
__global__ void splitconv(const float* __restrict__ x,
                          __nv_bfloat16* __restrict__ oh, __nv_bfloat16* __restrict__ ol)
{
    int idx = (blockIdx.x * 256 + threadIdx.x) * 4;
    float4 v = *(const float4*)(x + idx);
    float h0,l0,h1,l1,h2,l2,h3,l3;
    splitf(v.x,h0,l0); splitf(v.y,h1,l1); splitf(v.z,h2,l2); splitf(v.w,h3,l3);
    unsigned* ph = (unsigned*)(oh + idx);
    unsigned* pl = (unsigned*)(ol + idx);
    ph[0] = packbf(h0,h1); ph[1] = packbf(h2,h3);
    pl[0] = packbf(l0,l1); pl[1] = packbf(l2,l3);
}

// ---------------- LayerNorm -> split bf16 ----------------
__global__ void ln_kernel(const float* __restrict__ x, const float* __restrict__ gam,
                          const float* __restrict__ bet,
                          __nv_bfloat16* __restrict__ oh, __nv_bfloat16* __restrict__ ol)
{
    int row = blockIdx.x;
    int t = threadIdx.x;
    const float* xr = x + (size_t)row * H_;
    float v0 = xr[t], v1 = xr[t+256], v2 = xr[t+512];
    float s  = v0 + v1 + v2;
    float sq = v0*v0 + v1*v1 + v2*v2;
    #pragma unroll
    for (int off = 16; off; off >>= 1) {
        s  += __shfl_xor_sync(~0u, s,  off);
        sq += __shfl_xor_sync(~0u, sq, off);
    }
    __shared__ float rs[8], rq[8];
    int w = t >> 5;
    if ((t & 31) == 0) { rs[w] = s; rq[w] = sq; }
    __syncthreads();
    if (t < 32) {
        float a  = (t < 8) ? rs[t] : 0.f;
        float b2 = (t < 8) ? rq[t] : 0.f;
        #pragma unroll
        for (int off = 4; off; off >>= 1) {
            a  += __shfl_xor_sync(~0u, a,  off);
            b2 += __shfl_xor_sync(~0u, b2, off);
        }
        if (t == 0) { rs[0] = a; rq[0] = b2; }
    }
    __syncthreads();
    float mu  = rs[0] * (1.f / H_);
    float var = rq[0] * (1.f / H_) - mu * mu;
    float r   = rsqrtf(var + 1e-5f);
    size_t base = (size_t)row * H_;
    #pragma unroll
    for (int e = 0; e < 3; e++) {
        int c = t + e * 256;
        float val = ((e==0?v0:e==1?v1:v2) - mu) * r * gam[c] + bet[c];
        float h, l; splitf(val, h, l);
        oh[base + c] = __float2bfloat16_rn(h);
        ol[base + c] = __float2bfloat16_rn(l);
    }
}

// ---------------- GEMM: [4096xH] @ W -> C, bf16-split mma (R2 proven) ----------------
#define GP 40
__global__ void __launch_bounds__(256) gemm_mma(
    const __nv_bfloat16* __restrict__ Ahi, const __nv_bfloat16* __restrict__ Alo,
    const __nv_bfloat16* __restrict__ Bhi, const __nv_bfloat16* __restrict__ Blo,
    const float* __restrict__ bias, const float* __restrict__ memadd,
    const float* __restrict__ gate, const float* __restrict__ gbias,
    const float* __restrict__ dyn,
    __nv_bfloat16* __restrict__ Chi, __nv_bfloat16* __restrict__ Clo,
    float* __restrict__ Cf, int mode)
{
    __shared__ __nv_bfloat16 As[2][128][GP];
    __shared__ __nv_bfloat16 Bs[2][128][GP];
    int t = threadIdx.x, w = t >> 5, lane = t & 31;
    int wm = w & 1, wn = w >> 1;
    int m0 = blockIdx.x * 128, n0 = blockIdx.y * 128;
    int g = lane >> 2, qd = lane & 3;

    float acc[4][4][4] = {};

    uint4 rah[2], ral[2], rbh[2], rbl[2];
    int lrow[2], lcol[2];
    #pragma unroll
    for (int i = 0; i < 2; i++) {
        int c = t + i * 256;
        lrow[i] = c >> 2; lcol[i] = (c & 3) * 8;
    }
    auto fetch = [&](int k0) {
        #pragma unroll
        for (int i = 0; i < 2; i++) {
            size_t ai = (size_t)(m0 + lrow[i]) * H_ + k0 + lcol[i];
            rah[i] = *(const uint4*)(Ahi + ai);
            ral[i] = *(const uint4*)(Alo + ai);
            size_t bi = (size_t)(n0 + lrow[i]) * H_ + k0 + lcol[i];
            rbh[i] = *(const uint4*)(Bhi + bi);
            rbl[i] = *(const uint4*)(Blo + bi);
        }
    };

    int lr = lane & 15, lc = (lane >> 4) * 8;
    unsigned aH = sa(&As[0][wm*64 + lr][lc]);
    unsigned aL = sa(&As[1][wm*64 + lr][lc]);
    unsigned bH = sa(&Bs[0][wn*32 + lr][lc]);
    unsigned bL = sa(&Bs[1][wn*32 + lr][lc]);

    fetch(0);
    for (int it = 0; it < H_/32; it++) {
        __syncthreads();
        #pragma unroll
        for (int i = 0; i < 2; i++) {
            *(uint4*)&As[0][lrow[i]][lcol[i]] = rah[i];
            *(uint4*)&As[1][lrow[i]][lcol[i]] = ral[i];
            *(uint4*)&Bs[0][lrow[i]][lcol[i]] = rbh[i];
            *(uint4*)&Bs[1][lrow[i]][lcol[i]] = rbl[i];
        }
        __syncthreads();
        if (it < H_/32 - 1) fetch((it + 1) * 32);

        #pragma unroll
        for (int kh = 0; kh < 2; kh++) {
            unsigned ah[4][4], al[4][4], bh[2][4], bl[2][4];
            #pragma unroll
            for (int mt = 0; mt < 4; mt++) {
                unsigned off = (mt*16*GP + kh*16) * 2;
                ldsm4(ah[mt], aH + off);
                ldsm4(al[mt], aL + off);
            }
            #pragma unroll
            for (int ng = 0; ng < 2; ng++) {
                unsigned off = (ng*16*GP + kh*16) * 2;
                ldsm4(bh[ng], bH + off);
                ldsm4(bl[ng], bL + off);
            }
            #pragma unroll
            for (int mt = 0; mt < 4; mt++)
                #pragma unroll
                for (int ng = 0; ng < 2; ng++)
                    #pragma unroll
                    for (int tl = 0; tl < 2; tl++) {
                        float* d = acc[mt][ng*2 + tl];
                        mma_bf16(d, ah[mt], bh[ng][tl], bh[ng][tl+2]);
                        mma_bf16(d, ah[mt], bl[ng][tl], bl[ng][tl+2]);
                        mma_bf16(d, al[mt], bh[ng][tl], bh[ng][tl+2]);
                    }
        }
    }

    float gv = 1.f, gb = 0.f;
    if (mode == 2) { gv = gate[0]; gb = gbias[0]; }
    #pragma unroll
    for (int mt = 0; mt < 4; mt++) {
        #pragma unroll
        for (int nt = 0; nt < 4; nt++) {
            int col = n0 + wn*32 + nt*8 + qd*2;
            float2 bv = *(const float2*)(bias + col);
            #pragma unroll
            for (int rj = 0; rj < 2; rj++) {
                int row = m0 + wm*64 + mt*16 + g + rj*8;
                float x0 = acc[mt][nt][rj*2]   + bv.x;
                float x1 = acc[mt][nt][rj*2+1] + bv.y;
                if (mode == 1) {
                    float2 mm = *(const float2*)(memadd + (size_t)row * H_ + col);
                    x0 += 0.5f * mm.x; x1 += 0.5f * mm.y;
                }
                if (mode == 2) {
                    float d = dyn[row];
                    x0 = (x0*gv + gb) * d; x1 = (x1*gv + gb) * d;
                    *(float2*)(Cf + (size_t)row * H_ + col) = make_float2(x0, x1);
                } else {
                    float h0,l0,h1,l1;
                    splitf(x0,h0,l0); splitf(x1,h1,l1);
                    size_t o = (size_t)row * H_ + col;
                    *(unsigned*)(Chi + o) = packbf(h0,h1);
                    *(unsigned*)(Clo + o) = packbf(l0,l1);
                }
            }
        }
    }
}

// ---------------- Flash attention, bf16-split mma, double-buffered cp.async ----------------
#define FP 72
#define MP 68
#define NKT (S_/64)      // 32 k-tiles
__global__ void __launch_bounds__(128) flash_mma(
    const __nv_bfloat16* __restrict__ qh, const __nv_bfloat16* __restrict__ ql,
    const __nv_bfloat16* __restrict__ kh, const __nv_bfloat16* __restrict__ kl,
    const __nv_bfloat16* __restrict__ vh, const __nv_bfloat16* __restrict__ vl,
    const int* __restrict__ mask,
    __nv_bfloat16* __restrict__ aoh, __nv_bfloat16* __restrict__ aol)
{
    extern __shared__ char fsm[];
    __nv_bfloat16* Qh = (__nv_bfloat16*)fsm;            // 64*FP
    __nv_bfloat16* Ql = Qh + 64*FP;                     // 64*FP
    __nv_bfloat16* KV = Ql + 64*FP;                     // [2 stages][4 planes][64*FP]
    unsigned char* Ms = (unsigned char*)(KV + 2*4*64*FP); // [2][64*MP]

    int t = threadIdx.x, w = t >> 5, lane = t & 31;
    int g = lane >> 2, qd = lane & 3;
    int q0 = blockIdx.x * 64, h = blockIdx.y, b = blockIdx.z;
    const size_t basec = (size_t)b * S_ * H_ + h * 64;
    const int* mb = mask + (size_t)b * S_ * S_;

    // load Q (regular)
    for (int i = t; i < 512; i += 128) {
        int r = i >> 3, c = (i & 7) * 8;
        size_t gi = basec + (size_t)(q0 + r) * H_ + c;
        *(uint4*)&Qh[r*FP + c] = *(const uint4*)(qh + gi);
        *(uint4*)&Ql[r*FP + c] = *(const uint4*)(ql + gi);
    }

    auto load_kv = [&](int k0, int s) {
        #pragma unroll
        for (int p = 0; p < 4; p++) {
            const __nv_bfloat16* src = p==0 ? kh : p==1 ? kl : p==2 ? vh : vl;
            __nv_bfloat16* dst = KV + (s*4 + p) * 64*FP;
            #pragma unroll
            for (int i = t; i < 512; i += 128) {
                int r = i >> 3, c = (i & 7) * 8;
                CP16(sa(dst + r*FP + c), src + basec + (size_t)(k0 + r) * H_ + c);
            }
        }
        CP_COMMIT();
    };
    auto load_mask = [&](int k0, int s) {
        unsigned char* msp = Ms + s * 64*MP;
        #pragma unroll
        for (int i = t; i < 1024; i += 128) {
            int r = i >> 4, c4 = (i & 15) * 4;
            int4 mv = *(const int4*)(mb + (size_t)(q0 + r) * S_ + k0 + c4);
            uchar4 u;
            u.x = mv.x != 0; u.y = mv.y != 0; u.z = mv.z != 0; u.w = mv.w != 0;
            *(uchar4*)&msp[r*MP + c4] = u;
        }
    };

    load_kv(0, 0);
    load_mask(0, 0);
    __syncthreads();   // Q visible for fragment loads

    int lr = lane & 15, lc = (lane >> 4) * 8;
    unsigned qfh[4][4], qfl[4][4];
    #pragma unroll
    for (int kb = 0; kb < 4; kb++) {
        ldsm4(qfh[kb], sa(&Qh[(w*16 + lr)*FP + lc + kb*16]));
        ldsm4(qfl[kb], sa(&Ql[(w*16 + lr)*FP + lc + kb*16]));
    }

    float mrow[2] = {-CUDART_INF_F, -CUDART_INF_F};
    float lrow_[2] = {0.f, 0.f};
    float oacc[8][4] = {};

    for (int j = 0; j < NKT; j++) {
        int s = j & 1;
        if (j + 1 < NKT) {
            load_kv((j + 1) * 64, s ^ 1);
            load_mask((j + 1) * 64, s ^ 1);
            CP_WAIT1();
        } else {
            CP_WAIT0();
        }
        __syncthreads();   // stage s (K/V + mask) visible to all

        const __nv_bfloat16* Khs = KV + (s*4 + 0) * 64*FP;
        const __nv_bfloat16* Kls = KV + (s*4 + 1) * 64*FP;
        const __nv_bfloat16* Vhs = KV + (s*4 + 2) * 64*FP;
        const __nv_bfloat16* Vls = KV + (s*4 + 3) * 64*FP;
        const unsigned char* msp = Ms + s * 64*MP;

        // S = Q K^T (split, 3-term)
        float sreg[8][4] = {};
        #pragma unroll
        for (int kb = 0; kb < 4; kb++) {
            #pragma unroll
            for (int ng = 0; ng < 4; ng++) {
                unsigned b4h[4], b4l[4];
                unsigned off = ((ng*16 + lr)*FP + lc + kb*16) * 2;
                ldsm4(b4h, sa(Khs) + off);
                ldsm4(b4l, sa(Kls) + off);
                #pragma unroll
                for (int tl = 0; tl < 2; tl++) {
                    float* d = sreg[ng*2 + tl];
                    mma_bf16(d, qfh[kb], b4h[tl], b4h[tl+2]);
                    mma_bf16(d, qfh[kb], b4l[tl], b4l[tl+2]);
                    mma_bf16(d, qfl[kb], b4h[tl], b4h[tl+2]);
                }
            }
        }

        // mask + scale
        #pragma unroll
        for (int nt = 0; nt < 8; nt++)
            #pragma unroll
            for (int jj = 0; jj < 4; jj++) {
                int row = w*16 + g + (jj >> 1) * 8;
                int col = nt*8 + qd*2 + (jj & 1);
                sreg[nt][jj] = msp[row*MP + col] ? sreg[nt][jj] * 0.125f : -CUDART_INF_F;
            }

        // online softmax (2 rows per thread)
        #pragma unroll
        for (int rj = 0; rj < 2; rj++) {
            float mx = -CUDART_INF_F;
            #pragma unroll
            for (int nt = 0; nt < 8; nt++)
                mx = fmaxf(mx, fmaxf(sreg[nt][rj*2], sreg[nt][rj*2+1]));
            mx = fmaxf(mx, __shfl_xor_sync(~0u, mx, 1));
            mx = fmaxf(mx, __shfl_xor_sync(~0u, mx, 2));
            float nm = fmaxf(mrow[rj], mx);
            float corr, rsum = 0.f;
            if (nm == -CUDART_INF_F) {
                corr = 1.f;
                #pragma unroll
                for (int nt = 0; nt < 8; nt++) { sreg[nt][rj*2] = 0.f; sreg[nt][rj*2+1] = 0.f; }
            } else {
                corr = __expf(mrow[rj] - nm);
                #pragma unroll
                for (int nt = 0; nt < 8; nt++) {
                    float p0 = __expf(sreg[nt][rj*2]   - nm);
                    float p1 = __expf(sreg[nt][rj*2+1] - nm);
                    sreg[nt][rj*2] = p0; sreg[nt][rj*2+1] = p1;
                    rsum += p0 + p1;
                }
            }
            rsum += __shfl_xor_sync(~0u, rsum, 1);
            rsum += __shfl_xor_sync(~0u, rsum, 2);
            mrow[rj] = nm;
            lrow_[rj] = lrow_[rj] * corr + rsum;
            #pragma unroll
            for (int nt = 0; nt < 8; nt++) {
                oacc[nt][rj*2]   *= corr;
                oacc[nt][rj*2+1] *= corr;
            }
        }

        // pack P -> A fragments (split)
        unsigned pfh[4][4], pfl[4][4];
        #pragma unroll
        for (int kb = 0; kb < 4; kb++) {
            #pragma unroll
            for (int half = 0; half < 2; half++) {
                int nt = kb*2 + half;
                float h0,l0,h1,l1;
                splitf(sreg[nt][0], h0, l0); splitf(sreg[nt][1], h1, l1);
                pfh[kb][half*2]   = packbf(h0, h1);
                pfl[kb][half*2]   = packbf(l0, l1);
                splitf(sreg[nt][2], h0, l0); splitf(sreg[nt][3], h1, l1);
                pfh[kb][half*2+1] = packbf(h0, h1);
                pfl[kb][half*2+1] = packbf(l0, l1);
            }
        }

        // O += P V (split, 3-term)
        #pragma unroll
        for (int kb = 0; kb < 4; kb++) {
            #pragma unroll
            for (int ng = 0; ng < 4; ng++) {
                unsigned v4h[4], v4l[4];
                unsigned off = ((kb*16 + lr)*FP + ng*16 + lc) * 2;
                ldsm4t(v4h, sa(Vhs) + off);
                ldsm4t(v4l, sa(Vls) + off);
                #pragma unroll
                for (int tl = 0; tl < 2; tl++) {
                    float* d = oacc[ng*2 + tl];
                    mma_bf16(d, pfh[kb], v4h[tl*2], v4h[tl*2+1]);
                    mma_bf16(d, pfh[kb], v4l[tl*2], v4l[tl*2+1]);
                    mma_bf16(d, pfl[kb], v4h[tl*2], v4h[tl*2+1]);
                }
            }
        }
        __syncthreads();   // stage s free for reuse at j+2
    }

    // epilogue
    #pragma unroll
    for (int rj = 0; rj < 2; rj++) {
        float inv = lrow_[rj] > 0.f ? 1.f / lrow_[rj] : 0.f;
        int row = q0 + w*16 + g + rj*8;
        #pragma unroll
        for (int nt = 0; nt < 8; nt++) {
            int col = nt*8 + qd*2;
            float x0 = oacc[nt][rj*2] * inv, x1 = oacc[nt][rj*2+1] * inv;
            float h0,l0,h1,l1;
            splitf(x0,h0,l0); splitf(x1,h1,l1);
            size_t o = basec + (size_t)row * H_ + col;
            *(unsigned*)(aoh + o) = packbf(h0,h1);
            *(unsigned*)(aol + o) = packbf(l0,l1);
        }
    }
}

#define FSMEM (int)((2 + 2*4) * 64 * FP * sizeof(__nv_bfloat16) + 2 * 64 * MP)  // 100864

// ---------------- launch ----------------
extern "C" void kernel_launch(void* const* d_in, const int* in_sizes, int n_in,
                              void* d_out, int out_size)
{
    const float* hidden = (const float*)d_in[0];
    const float* cross  = (const float*)d_in[1];
    const int*   amask  = (const int*)  d_in[2];
    const float* mem    = (const float*)d_in[3];
    const float* dyn    = (const float*)d_in[4];
    const float* Wq = (const float*)d_in[5];  const float* bq = (const float*)d_in[6];
    const float* Wk = (const float*)d_in[7];  const float* bk = (const float*)d_in[8];
    const float* Wv = (const float*)d_in[9];  const float* bv = (const float*)d_in[10];
    const float* Wo = (const float*)d_in[11]; const float* bo = (const float*)d_in[12];
    const float* gate  = (const float*)d_in[13];
    const float* gbias = (const float*)d_in[14];
    const float* lng   = (const float*)d_in[15];
    const float* lnb   = (const float*)d_in[16];
    float* out = (float*)d_out;

    __nv_bfloat16 *xnh,*xnl,*crh,*crl,*qhp,*qlp,*khp,*klp,*vhp,*vlp,*aoh,*aol,*wth,*wtl;
    cudaGetSymbolAddress((void**)&xnh, g_xn_hi); cudaGetSymbolAddress((void**)&xnl, g_xn_lo);
    cudaGetSymbolAddress((void**)&crh, g_cr_hi); cudaGetSymbolAddress((void**)&crl, g_cr_lo);
    cudaGetSymbolAddress((void**)&qhp, g_q_hi);  cudaGetSymbolAddress((void**)&qlp, g_q_lo);
    cudaGetSymbolAddress((void**)&khp, g_k_hi);  cudaGetSymbolAddress((void**)&klp, g_k_lo);
    cudaGetSymbolAddress((void**)&vhp, g_v_hi);  cudaGetSymbolAddress((void**)&vlp, g_v_lo);
    cudaGetSymbolAddress((void**)&aoh, g_ao_hi); cudaGetSymbolAddress((void**)&aol, g_ao_lo);
    cudaGetSymbolAddress((void**)&wth, g_wt_hi); cudaGetSymbolAddress((void**)&wtl, g_wt_lo);

    wprep4<<<dim3(H_/32, H_/32, 4), dim3(32,8)>>>(Wq, Wk, Wv, Wo, wth, wtl);
    ln_kernel<<<ROWS, 256>>>(hidden, lng, lnb, xnh, xnl);
    splitconv<<<ROWS*H_/1024, 256>>>(cross, crh, crl);

    dim3 gg(ROWS/128, H_/128);
    gemm_mma<<<gg, 256>>>(xnh, xnl, wth + 0*H_*H_, wtl + 0*H_*H_,
                          bq, nullptr, nullptr, nullptr, nullptr, qhp, qlp, nullptr, 0);
    gemm_mma<<<gg, 256>>>(crh, crl, wth + 1*H_*H_, wtl + 1*H_*H_,
                          bk, mem, nullptr, nullptr, nullptr, khp, klp, nullptr, 1);
    gemm_mma<<<gg, 256>>>(crh, crl, wth + 2*H_*H_, wtl + 2*H_*H_,
                          bv, mem + (size_t)ROWS*H_, nullptr, nullptr, nullptr, vhp, vlp, nullptr, 1);

    cudaFuncSetAttribute(flash_mma, cudaFuncAttributeMaxDynamicSharedMemorySize, FSMEM);
    flash_mma<<<dim3(S_/64, NH_, B_), 128, FSMEM>>>(qhp, qlp, khp, klp, vhp, vlp, amask, aoh, aol);

    gemm_mma<<<gg, 256>>>(aoh, aol, wth + 3*H_*H_, wtl + 3*H_*H_,
                          bo, nullptr, gate, gbias, dyn, nullptr, nullptr, out, 2);
}

// round 5
// speedup vs baseline: 2.6355x; 1.1610x over previous
#include <cuda_runtime.h>
#include <cuda_bf16.h>
#include <math_constants.h>
#include <cstdint>

#define B_   2
#define S_   2048
#define H_   768
#define NH_  12
#define HD_  64
#define ROWS (B_*S_)          // 4096

// ---------------- scratch (bf16 hi/lo split operands) ----------------
__device__ __align__(256) __nv_bfloat16 g_xn_hi[ROWS*H_];
__device__ __align__(256) __nv_bfloat16 g_xn_lo[ROWS*H_];
__device__ __align__(256) __nv_bfloat16 g_cr_hi[ROWS*H_];
__device__ __align__(256) __nv_bfloat16 g_cr_lo[ROWS*H_];
__device__ __align__(256) __nv_bfloat16 g_q_hi [ROWS*H_];
__device__ __align__(256) __nv_bfloat16 g_q_lo [ROWS*H_];
__device__ __align__(256) __nv_bfloat16 g_k_hi [ROWS*H_];
__device__ __align__(256) __nv_bfloat16 g_k_lo [ROWS*H_];
__device__ __align__(256) __nv_bfloat16 g_v_hi [ROWS*H_];
__device__ __align__(256) __nv_bfloat16 g_v_lo [ROWS*H_];
__device__ __align__(256) __nv_bfloat16 g_ao_hi[ROWS*H_];
__device__ __align__(256) __nv_bfloat16 g_ao_lo[ROWS*H_];
__device__ __align__(256) __nv_bfloat16 g_wt_hi[4*H_*H_];
__device__ __align__(256) __nv_bfloat16 g_wt_lo[4*H_*H_];

// ---------------- helpers ----------------
__device__ __forceinline__ unsigned sa(const void* p) {
    return (unsigned)__cvta_generic_to_shared(p);
}
__device__ __forceinline__ void ldsm4(unsigned r[4], unsigned addr) {
    asm volatile("ldmatrix.sync.aligned.m8n8.x4.shared.b16 {%0,%1,%2,%3}, [%4];"
        : "=r"(r[0]), "=r"(r[1]), "=r"(r[2]), "=r"(r[3]) : "r"(addr));
}
__device__ __forceinline__ void ldsm4t(unsigned r[4], unsigned addr) {
    asm volatile("ldmatrix.sync.aligned.m8n8.x4.trans.shared.b16 {%0,%1,%2,%3}, [%4];"
        : "=r"(r[0]), "=r"(r[1]), "=r"(r[2]), "=r"(r[3]) : "r"(addr));
}
__device__ __forceinline__ void mma_bf16(float d[4], const unsigned a[4],
                                         unsigned b0, unsigned b1) {
    asm volatile("mma.sync.aligned.m16n8k16.row.col.f32.bf16.bf16.f32 "
        "{%0,%1,%2,%3}, {%4,%5,%6,%7}, {%8,%9}, {%0,%1,%2,%3};"
        : "+f"(d[0]), "+f"(d[1]), "+f"(d[2]), "+f"(d[3])
        : "r"(a[0]), "r"(a[1]), "r"(a[2]), "r"(a[3]), "r"(b0), "r"(b1));
}
__device__ __forceinline__ unsigned packbf(float lo, float hi) {
    unsigned r;
    asm("cvt.rn.bf16x2.f32 %0, %1, %2;" : "=r"(r) : "f"(hi), "f"(lo));
    return r;
}
__device__ __forceinline__ void splitf(float x, float& h, float& l) {
    __nv_bfloat16 bh = __float2bfloat16_rn(x);
    h = __bfloat162float(bh);
    l = x - h;
}
#define CP16(saddr, gptr) \
    asm volatile("cp.async.cg.shared.global [%0], [%1], 16;" :: "r"(saddr), "l"(gptr))
#define CP_COMMIT() asm volatile("cp.async.commit_group;" ::: "memory")
#define CP_WAIT0() asm volatile("cp.async.wait_group 0;" ::: "memory")
#define CP_WAIT1() asm volatile("cp.async.wait_group 1;" ::: "memory")

// ---------------- weight prep: transpose + split (4 matrices, one launch) ----------------
__global__ void wprep4(const float* __restrict__ W0, const float* __restrict__ W1,
                       const float* __restrict__ W2, const float* __restrict__ W3,
                       __nv_bfloat16* __restrict__ Th, __nv_bfloat16* __restrict__ Tl)
{
    __shared__ float tile[32][33];
    int z = blockIdx.z;
    const float* W = z == 0 ? W0 : z == 1 ? W1 : z == 2 ? W2 : W3;
    __nv_bfloat16* th = Th + (size_t)z * H_ * H_;
    __nv_bfloat16* tl = Tl + (size_t)z * H_ * H_;
    int k0 = blockIdx.x * 32, n0 = blockIdx.y * 32;
    int tx = threadIdx.x, ty = threadIdx.y;          // 32 x 8
    for (int i = ty; i < 32; i += 8)
        tile[i][tx] = W[(size_t)(k0 + i) * H_ + n0 + tx];
    __syncthreads();
    for (int i = ty; i < 32; i += 8) {
        float v = tile[tx][i];
        float h, l; splitf(v, h, l);
        size_t o = (size_t)(n0 + i) * H_ + k0 + tx;
        th[o] = __float2bfloat16_rn(h);
        tl[o] = __float2bfloat16_rn(l);
    }
}

// ---------------- elementwise split (cross_states) ----------------
__global__ void splitconv(const float* __restrict__ x,
                          __nv_bfloat16* __restrict__ oh, __nv_bfloat16* __restrict__ ol)
{
    int idx = (blockIdx.x * 256 + threadIdx.x) * 4;
    float4 v = *(const float4*)(x + idx);
    float h0,l0,h1,l1,h2,l2,h3,l3;
    splitf(v.x,h0,l0); splitf(v.y,h1,l1); splitf(v.z,h2,l2); splitf(v.w,h3,l3);
    unsigned* ph = (unsigned*)(oh + idx);
    unsigned* pl = (unsigned*)(ol + idx);
    ph[0] = packbf(h0,h1); ph[1] = packbf(h2,h3);
    pl[0] = packbf(l0,l1); pl[1] = packbf(l2,l3);
}

// ---------------- LayerNorm -> split bf16 ----------------
__global__ void ln_kernel(const float* __restrict__ x, const float* __restrict__ gam,
                          const float* __restrict__ bet,
                          __nv_bfloat16* __restrict__ oh, __nv_bfloat16* __restrict__ ol)
{
    int row = blockIdx.x;
    int t = threadIdx.x;
    const float* xr = x + (size_t)row * H_;
    float v0 = xr[t], v1 = xr[t+256], v2 = xr[t+512];
    float s  = v0 + v1 + v2;
    float sq = v0*v0 + v1*v1 + v2*v2;
    #pragma unroll
    for (int off = 16; off; off >>= 1) {
        s  += __shfl_xor_sync(~0u, s,  off);
        sq += __shfl_xor_sync(~0u, sq, off);
    }
    __shared__ float rs[8], rq[8];
    int w = t >> 5;
    if ((t & 31) == 0) { rs[w] = s; rq[w] = sq; }
    __syncthreads();
    if (t < 32) {
        float a  = (t < 8) ? rs[t] : 0.f;
        float b2 = (t < 8) ? rq[t] : 0.f;
        #pragma unroll
        for (int off = 4; off; off >>= 1) {
            a  += __shfl_xor_sync(~0u, a,  off);
            b2 += __shfl_xor_sync(~0u, b2, off);
        }
        if (t == 0) { rs[0] = a; rq[0] = b2; }
    }
    __syncthreads();
    float mu  = rs[0] * (1.f / H_);
    float var = rq[0] * (1.f / H_) - mu * mu;
    float r   = rsqrtf(var + 1e-5f);
    size_t base = (size_t)row * H_;
    #pragma unroll
    for (int e = 0; e < 3; e++) {
        int c = t + e * 256;
        float val = ((e==0?v0:e==1?v1:v2) - mu) * r * gam[c] + bet[c];
        float h, l; splitf(val, h, l);
        oh[base + c] = __float2bfloat16_rn(h);
        ol[base + c] = __float2bfloat16_rn(l);
    }
}

// ---------------- GEMM: cp.async 2-stage pipeline, bf16-split mma ----------------
// fused=0: blockIdx.z selects Q(z0)/K(z1)/V(z2) projection (mode 0/1/1)
// fused=1: output projection with gate/dyn epilogue (mode 2)
#define GP2 40
#define GPLANE (128*GP2)   // halfs per plane
// smem: stage s (0/1), plane p (0=Ahi,1=Alo,2=Bhi,3=Blo) at (s*4+p)*GPLANE
#define GSMEM (int)(2*4*GPLANE*sizeof(__nv_bfloat16))   // 81920

__global__ void __launch_bounds__(256, 2) gemm_qkv(
    const __nv_bfloat16* __restrict__ xnh, const __nv_bfloat16* __restrict__ xnl,
    const __nv_bfloat16* __restrict__ crh, const __nv_bfloat16* __restrict__ crl,
    const __nv_bfloat16* __restrict__ wth, const __nv_bfloat16* __restrict__ wtl,
    const float* __restrict__ bq, const float* __restrict__ bk, const float* __restrict__ bv,
    const float* __restrict__ mem,
    const float* __restrict__ gate, const float* __restrict__ gbias,
    const float* __restrict__ dyn,
    __nv_bfloat16* __restrict__ qhp, __nv_bfloat16* __restrict__ qlp,
    __nv_bfloat16* __restrict__ khp, __nv_bfloat16* __restrict__ klp,
    __nv_bfloat16* __restrict__ vhp, __nv_bfloat16* __restrict__ vlp,
    float* __restrict__ Cf, int fused)
{
    extern __shared__ __nv_bfloat16 gsm[];
    int t = threadIdx.x, w = t >> 5, lane = t & 31;
    int wm = w & 1, wn = w >> 1;
    int m0 = blockIdx.x * 128, n0 = blockIdx.y * 128;
    int g = lane >> 2, qd = lane & 3;
    int z = blockIdx.z;

    const __nv_bfloat16 *Ahi, *Alo, *Bhi, *Blo;
    const float *bias, *memadd = nullptr;
    __nv_bfloat16 *Chi = nullptr, *Clo = nullptr;
    int mode;
    if (fused) {
        Ahi = xnh; Alo = xnl;                      // caller passes ao in xn slots
        Bhi = wth; Blo = wtl;                      // caller passes Wo^T base
        bias = bq; mode = 2;
    } else if (z == 0) {
        Ahi = xnh; Alo = xnl;
        Bhi = wth; Blo = wtl;
        bias = bq; mode = 0; Chi = qhp; Clo = qlp;
    } else if (z == 1) {
        Ahi = crh; Alo = crl;
        Bhi = wth + (size_t)H_*H_; Blo = wtl + (size_t)H_*H_;
        bias = bk; mode = 1; memadd = mem; Chi = khp; Clo = klp;
    } else {
        Ahi = crh; Alo = crl;
        Bhi = wth + 2*(size_t)H_*H_; Blo = wtl + 2*(size_t)H_*H_;
        bias = bv; mode = 1; memadd = mem + (size_t)ROWS*H_; Chi = vhp; Clo = vlp;
    }

    // stage loader: 512 16B-chunks per plane, 2 per thread
    auto load_stage = [&](int k0, int s) {
        #pragma unroll
        for (int p = 0; p < 4; p++) {
            const __nv_bfloat16* src = p == 0 ? Ahi : p == 1 ? Alo : p == 2 ? Bhi : Blo;
            int rbase = (p < 2) ? m0 : n0;
            __nv_bfloat16* dst = gsm + (s*4 + p) * GPLANE;
            #pragma unroll
            for (int i = t; i < 512; i += 256) {
                int r = i >> 2, c = (i & 3) * 8;
                CP16(sa(dst + r*GP2 + c), src + (size_t)(rbase + r) * H_ + k0 + c);
            }
        }
        CP_COMMIT();
    };

    float acc[4][4][4] = {};
    int lr = lane & 15, lc = (lane >> 4) * 8;

    load_stage(0, 0);
    const int NIT = H_ / 32;           // 24
    for (int j = 0; j < NIT; j++) {
        int s = j & 1;
        if (j + 1 < NIT) { load_stage((j + 1) * 32, s ^ 1); CP_WAIT1(); }
        else             { CP_WAIT0(); }
        __syncthreads();

        unsigned aH = sa(gsm + (s*4 + 0)*GPLANE + (wm*64 + lr)*GP2 + lc);
        unsigned aL = sa(gsm + (s*4 + 1)*GPLANE + (wm*64 + lr)*GP2 + lc);
        unsigned bH = sa(gsm + (s*4 + 2)*GPLANE + (wn*32 + lr)*GP2 + lc);
        unsigned bL = sa(gsm + (s*4 + 3)*GPLANE + (wn*32 + lr)*GP2 + lc);

        #pragma unroll
        for (int kh = 0; kh < 2; kh++) {
            unsigned ah[4][4], al[4][4], bh[2][4], bl[2][4];
            #pragma unroll
            for (int mt = 0; mt < 4; mt++) {
                unsigned off = (mt*16*GP2 + kh*16) * 2;
                ldsm4(ah[mt], aH + off);
                ldsm4(al[mt], aL + off);
            }
            #pragma unroll
            for (int ng = 0; ng < 2; ng++) {
                unsigned off = (ng*16*GP2 + kh*16) * 2;
                ldsm4(bh[ng], bH + off);
                ldsm4(bl[ng], bL + off);
            }
            #pragma unroll
            for (int mt = 0; mt < 4; mt++)
                #pragma unroll
                for (int ng = 0; ng < 2; ng++)
                    #pragma unroll
                    for (int tl = 0; tl < 2; tl++) {
                        float* d = acc[mt][ng*2 + tl];
                        mma_bf16(d, ah[mt], bh[ng][tl], bh[ng][tl+2]);
                        mma_bf16(d, ah[mt], bl[ng][tl], bl[ng][tl+2]);
                        mma_bf16(d, al[mt], bh[ng][tl], bh[ng][tl+2]);
                    }
        }
        __syncthreads();
    }

    float gv = 1.f, gb = 0.f;
    if (mode == 2) { gv = gate[0]; gb = gbias[0]; }
    #pragma unroll
    for (int mt = 0; mt < 4; mt++) {
        #pragma unroll
        for (int nt = 0; nt < 4; nt++) {
            int col = n0 + wn*32 + nt*8 + qd*2;
            float2 bvv = *(const float2*)(bias + col);
            #pragma unroll
            for (int rj = 0; rj < 2; rj++) {
                int row = m0 + wm*64 + mt*16 + g + rj*8;
                float x0 = acc[mt][nt][rj*2]   + bvv.x;
                float x1 = acc[mt][nt][rj*2+1] + bvv.y;
                if (mode == 1) {
                    float2 mm = *(const float2*)(memadd + (size_t)row * H_ + col);
                    x0 += 0.5f * mm.x; x1 += 0.5f * mm.y;
                }
                if (mode == 2) {
                    float d = dyn[row];
                    x0 = (x0*gv + gb) * d; x1 = (x1*gv + gb) * d;
                    *(float2*)(Cf + (size_t)row * H_ + col) = make_float2(x0, x1);
                } else {
                    float h0,l0,h1,l1;
                    splitf(x0,h0,l0); splitf(x1,h1,l1);
                    size_t o = (size_t)row * H_ + col;
                    *(unsigned*)(Chi + o) = packbf(h0,h1);
                    *(unsigned*)(Clo + o) = packbf(l0,l1);
                }
            }
        }
    }
}

// ---------------- Flash attention, bf16-split mma, double-buffered cp.async ----------------
#define FP 72
#define MP 68
#define NKT (S_/64)      // 32 k-tiles
__global__ void __launch_bounds__(128) flash_mma(
    const __nv_bfloat16* __restrict__ qh, const __nv_bfloat16* __restrict__ ql,
    const __nv_bfloat16* __restrict__ kh, const __nv_bfloat16* __restrict__ kl,
    const __nv_bfloat16* __restrict__ vh, const __nv_bfloat16* __restrict__ vl,
    const int* __restrict__ mask,
    __nv_bfloat16* __restrict__ aoh, __nv_bfloat16* __restrict__ aol)
{
    extern __shared__ char fsm[];
    __nv_bfloat16* Qh = (__nv_bfloat16*)fsm;
    __nv_bfloat16* Ql = Qh + 64*FP;
    __nv_bfloat16* KV = Ql + 64*FP;
    unsigned char* Ms = (unsigned char*)(KV + 2*4*64*FP);

    int t = threadIdx.x, w = t >> 5, lane = t & 31;
    int g = lane >> 2, qd = lane & 3;
    int q0 = blockIdx.x * 64, h = blockIdx.y, b = blockIdx.z;
    const size_t basec = (size_t)b * S_ * H_ + h * 64;
    const int* mb = mask + (size_t)b * S_ * S_;

    for (int i = t; i < 512; i += 128) {
        int r = i >> 3, c = (i & 7) * 8;
        size_t gi = basec + (size_t)(q0 + r) * H_ + c;
        *(uint4*)&Qh[r*FP + c] = *(const uint4*)(qh + gi);
        *(uint4*)&Ql[r*FP + c] = *(const uint4*)(ql + gi);
    }

    auto load_kv = [&](int k0, int s) {
        #pragma unroll
        for (int p = 0; p < 4; p++) {
            const __nv_bfloat16* src = p==0 ? kh : p==1 ? kl : p==2 ? vh : vl;
            __nv_bfloat16* dst = KV + (s*4 + p) * 64*FP;
            #pragma unroll
            for (int i = t; i < 512; i += 128) {
                int r = i >> 3, c = (i & 7) * 8;
                CP16(sa(dst + r*FP + c), src + basec + (size_t)(k0 + r) * H_ + c);
            }
        }
        CP_COMMIT();
    };
    auto load_mask = [&](int k0, int s) {
        unsigned char* msp = Ms + s * 64*MP;
        #pragma unroll
        for (int i = t; i < 1024; i += 128) {
            int r = i >> 4, c4 = (i & 15) * 4;
            int4 mv = *(const int4*)(mb + (size_t)(q0 + r) * S_ + k0 + c4);
            uchar4 u;
            u.x = mv.x != 0; u.y = mv.y != 0; u.z = mv.z != 0; u.w = mv.w != 0;
            *(uchar4*)&msp[r*MP + c4] = u;
        }
    };

    load_kv(0, 0);
    load_mask(0, 0);
    __syncthreads();

    int lr = lane & 15, lc = (lane >> 4) * 8;
    unsigned qfh[4][4], qfl[4][4];
    #pragma unroll
    for (int kb = 0; kb < 4; kb++) {
        ldsm4(qfh[kb], sa(&Qh[(w*16 + lr)*FP + lc + kb*16]));
        ldsm4(qfl[kb], sa(&Ql[(w*16 + lr)*FP + lc + kb*16]));
    }

    float mrow[2] = {-CUDART_INF_F, -CUDART_INF_F};
    float lrow_[2] = {0.f, 0.f};
    float oacc[8][4] = {};

    for (int j = 0; j < NKT; j++) {
        int s = j & 1;
        if (j + 1 < NKT) {
            load_kv((j + 1) * 64, s ^ 1);
            load_mask((j + 1) * 64, s ^ 1);
            CP_WAIT1();
        } else {
            CP_WAIT0();
        }
        __syncthreads();

        const __nv_bfloat16* Khs = KV + (s*4 + 0) * 64*FP;
        const __nv_bfloat16* Kls = KV + (s*4 + 1) * 64*FP;
        const __nv_bfloat16* Vhs = KV + (s*4 + 2) * 64*FP;
        const __nv_bfloat16* Vls = KV + (s*4 + 3) * 64*FP;
        const unsigned char* msp = Ms + s * 64*MP;

        float sreg[8][4] = {};
        #pragma unroll
        for (int kb = 0; kb < 4; kb++) {
            #pragma unroll
            for (int ng = 0; ng < 4; ng++) {
                unsigned b4h[4], b4l[4];
                unsigned off = ((ng*16 + lr)*FP + lc + kb*16) * 2;
                ldsm4(b4h, sa(Khs) + off);
                ldsm4(b4l, sa(Kls) + off);
                #pragma unroll
                for (int tl = 0; tl < 2; tl++) {
                    float* d = sreg[ng*2 + tl];
                    mma_bf16(d, qfh[kb], b4h[tl], b4h[tl+2]);
                    mma_bf16(d, qfh[kb], b4l[tl], b4l[tl+2]);
                    mma_bf16(d, qfl[kb], b4h[tl], b4h[tl+2]);
                }
            }
        }

        #pragma unroll
        for (int nt = 0; nt < 8; nt++)
            #pragma unroll
            for (int jj = 0; jj < 4; jj++) {
                int row = w*16 + g + (jj >> 1) * 8;
                int col = nt*8 + qd*2 + (jj & 1);
                sreg[nt][jj] = msp[row*MP + col] ? sreg[nt][jj] * 0.125f : -CUDART_INF_F;
            }

        #pragma unroll
        for (int rj = 0; rj < 2; rj++) {
            float mx = -CUDART_INF_F;
            #pragma unroll
            for (int nt = 0; nt < 8; nt++)
                mx = fmaxf(mx, fmaxf(sreg[nt][rj*2], sreg[nt][rj*2+1]));
            mx = fmaxf(mx, __shfl_xor_sync(~0u, mx, 1));
            mx = fmaxf(mx, __shfl_xor_sync(~0u, mx, 2));
            float nm = fmaxf(mrow[rj], mx);
            float corr, rsum = 0.f;
            if (nm == -CUDART_INF_F) {
                corr = 1.f;
                #pragma unroll
                for (int nt = 0; nt < 8; nt++) { sreg[nt][rj*2] = 0.f; sreg[nt][rj*2+1] = 0.f; }
            } else {
                corr = __expf(mrow[rj] - nm);
                #pragma unroll
                for (int nt = 0; nt < 8; nt++) {
                    float p0 = __expf(sreg[nt][rj*2]   - nm);
                    float p1 = __expf(sreg[nt][rj*2+1] - nm);
                    sreg[nt][rj*2] = p0; sreg[nt][rj*2+1] = p1;
                    rsum += p0 + p1;
                }
            }
            rsum += __shfl_xor_sync(~0u, rsum, 1);
            rsum += __shfl_xor_sync(~0u, rsum, 2);
            mrow[rj] = nm;
            lrow_[rj] = lrow_[rj] * corr + rsum;
            #pragma unroll
            for (int nt = 0; nt < 8; nt++) {
                oacc[nt][rj*2]   *= corr;
                oacc[nt][rj*2+1] *= corr;
            }
        }

        unsigned pfh[4][4], pfl[4][4];
        #pragma unroll
        for (int kb = 0; kb < 4; kb++) {
            #pragma unroll
            for (int half = 0; half < 2; half++) {
                int nt = kb*2 + half;
                float h0,l0,h1,l1;
                splitf(sreg[nt][0], h0, l0); splitf(sreg[nt][1], h1, l1);
                pfh[kb][half*2]   = packbf(h0, h1);
                pfl[kb][half*2]   = packbf(l0, l1);
                splitf(sreg[nt][2], h0, l0); splitf(sreg[nt][3], h1, l1);
                pfh[kb][half*2+1] = packbf(h0, h1);
                pfl[kb][half*2+1] = packbf(l0, l1);
            }
        }

        #pragma unroll
        for (int kb = 0; kb < 4; kb++) {
            #pragma unroll
            for (int ng = 0; ng < 4; ng++) {
                unsigned v4h[4], v4l[4];
                unsigned off = ((kb*16 + lr)*FP + ng*16 + lc) * 2;
                ldsm4t(v4h, sa(Vhs) + off);
                ldsm4t(v4l, sa(Vls) + off);
                #pragma unroll
                for (int tl = 0; tl < 2; tl++) {
                    float* d = oacc[ng*2 + tl];
                    mma_bf16(d, pfh[kb], v4h[tl*2], v4h[tl*2+1]);
                    mma_bf16(d, pfh[kb], v4l[tl*2], v4l[tl*2+1]);
                    mma_bf16(d, pfl[kb], v4h[tl*2], v4h[tl*2+1]);
                }
            }
        }
        __syncthreads();
    }

    #pragma unroll
    for (int rj = 0; rj < 2; rj++) {
        float inv = lrow_[rj] > 0.f ? 1.f / lrow_[rj] : 0.f;
        int row = q0 + w*16 + g + rj*8;
        #pragma unroll
        for (int nt = 0; nt < 8; nt++) {
            int col = nt*8 + qd*2;
            float x0 = oacc[nt][rj*2] * inv, x1 = oacc[nt][rj*2+1] * inv;
            float h0,l0,h1,l1;
            splitf(x0,h0,l0); splitf(x1,h1,l1);
            size_t o = basec + (size_t)row * H_ + col;
            *(unsigned*)(aoh + o) = packbf(h0,h1);
            *(unsigned*)(aol + o) = packbf(l0,l1);
        }
    }
}

#define FSMEM (int)((2 + 2*4) * 64 * FP * sizeof(__nv_bfloat16) + 2 * 64 * MP)  // 100864

// ---------------- launch ----------------
extern "C" void kernel_launch(void* const* d_in, const int* in_sizes, int n_in,
                              void* d_out, int out_size)
{
    const float* hidden = (const float*)d_in[0];
    const float* cross  = (const float*)d_in[1];
    const int*   amask  = (const int*)  d_in[2];
    const float* mem    = (const float*)d_in[3];
    const float* dyn    = (const float*)d_in[4];
    const float* Wq = (const float*)d_in[5];  const float* bq = (const float*)d_in[6];
    const float* Wk = (const float*)d_in[7];  const float* bk = (const float*)d_in[8];
    const float* Wv = (const float*)d_in[9];  const float* bv = (const float*)d_in[10];
    const float* Wo = (const float*)d_in[11]; const float* bo = (const float*)d_in[12];
    const float* gate  = (const float*)d_in[13];
    const float* gbias = (const float*)d_in[14];
    const float* lng   = (const float*)d_in[15];
    const float* lnb   = (const float*)d_in[16];
    float* out = (float*)d_out;

    __nv_bfloat16 *xnh,*xnl,*crh,*crl,*qhp,*qlp,*khp,*klp,*vhp,*vlp,*aoh,*aol,*wth,*wtl;
    cudaGetSymbolAddress((void**)&xnh, g_xn_hi); cudaGetSymbolAddress((void**)&xnl, g_xn_lo);
    cudaGetSymbolAddress((void**)&crh, g_cr_hi); cudaGetSymbolAddress((void**)&crl, g_cr_lo);
    cudaGetSymbolAddress((void**)&qhp, g_q_hi);  cudaGetSymbolAddress((void**)&qlp, g_q_lo);
    cudaGetSymbolAddress((void**)&khp, g_k_hi);  cudaGetSymbolAddress((void**)&klp, g_k_lo);
    cudaGetSymbolAddress((void**)&vhp, g_v_hi);  cudaGetSymbolAddress((void**)&vlp, g_v_lo);
    cudaGetSymbolAddress((void**)&aoh, g_ao_hi); cudaGetSymbolAddress((void**)&aol, g_ao_lo);
    cudaGetSymbolAddress((void**)&wth, g_wt_hi); cudaGetSymbolAddress((void**)&wtl, g_wt_lo);

    cudaFuncSetAttribute(gemm_qkv, cudaFuncAttributeMaxDynamicSharedMemorySize, GSMEM);
    cudaFuncSetAttribute(flash_mma, cudaFuncAttributeMaxDynamicSharedMemorySize, FSMEM);

    wprep4<<<dim3(H_/32, H_/32, 4), dim3(32,8)>>>(Wq, Wk, Wv, Wo, wth, wtl);
    ln_kernel<<<ROWS, 256>>>(hidden, lng, lnb, xnh, xnl);
    splitconv<<<ROWS*H_/1024, 256>>>(cross, crh, crl);

    // fused Q/K/V projection (z selects)
    gemm_qkv<<<dim3(ROWS/128, H_/128, 3), 256, GSMEM>>>(
        xnh, xnl, crh, crl, wth, wtl, bq, bk, bv, mem,
        nullptr, nullptr, nullptr,
        qhp, qlp, khp, klp, vhp, vlp, nullptr, 0);

    flash_mma<<<dim3(S_/64, NH_, B_), 128, FSMEM>>>(qhp, qlp, khp, klp, vhp, vlp, amask, aoh, aol);

    // output projection (pass ao via A slots, Wo^T via wt slots)
    gemm_qkv<<<dim3(ROWS/128, H_/128, 1), 256, GSMEM>>>(
        aoh, aol, nullptr, nullptr, wth + 3*(size_t)H_*H_, wtl + 3*(size_t)H_*H_,
        bo, nullptr, nullptr, nullptr,
        gate, gbias, dyn,
        nullptr, nullptr, nullptr, nullptr, nullptr, nullptr, out, 1);
}

// round 6
// speedup vs baseline: 2.9245x; 1.1097x over previous
#include <cuda_runtime.h>
#include <cuda_bf16.h>
#include <cuda_fp16.h>
#include <math_constants.h>
#include <cstdint>

#define B_   2
#define S_   2048
#define H_   768
#define NH_  12
#define HD_  64
#define ROWS (B_*S_)          // 4096

// ---------------- scratch ----------------
__device__ __align__(256) __nv_bfloat16 g_xn_hi[ROWS*H_];
__device__ __align__(256) __nv_bfloat16 g_xn_lo[ROWS*H_];
__device__ __align__(256) __nv_bfloat16 g_cr_hi[ROWS*H_];
__device__ __align__(256) __nv_bfloat16 g_cr_lo[ROWS*H_];
__device__ __align__(256) __nv_bfloat16 g_q_hi [ROWS*H_];
__device__ __align__(256) __nv_bfloat16 g_q_lo [ROWS*H_];
__device__ __align__(256) __nv_bfloat16 g_k_hi [ROWS*H_];
__device__ __align__(256) __nv_bfloat16 g_k_lo [ROWS*H_];
__device__ __align__(256) __nv_bfloat16 g_v_hi [ROWS*H_];   // holds fp16 bits
__device__ __align__(256) __nv_bfloat16 g_v_lo [ROWS*H_];   // holds fp16 bits
__device__ __align__(256) __nv_bfloat16 g_ao_hi[ROWS*H_];
__device__ __align__(256) __nv_bfloat16 g_ao_lo[ROWS*H_];
__device__ __align__(256) __nv_bfloat16 g_wt_hi[4*H_*H_];
__device__ __align__(256) __nv_bfloat16 g_wt_lo[4*H_*H_];
__device__ __align__(256) unsigned char g_mask8[(size_t)B_*S_*S_];   // 8.4 MB

// ---------------- helpers ----------------
__device__ __forceinline__ unsigned sa(const void* p) {
    return (unsigned)__cvta_generic_to_shared(p);
}
__device__ __forceinline__ void ldsm4(unsigned r[4], unsigned addr) {
    asm volatile("ldmatrix.sync.aligned.m8n8.x4.shared.b16 {%0,%1,%2,%3}, [%4];"
        : "=r"(r[0]), "=r"(r[1]), "=r"(r[2]), "=r"(r[3]) : "r"(addr));
}
__device__ __forceinline__ void ldsm4t(unsigned r[4], unsigned addr) {
    asm volatile("ldmatrix.sync.aligned.m8n8.x4.trans.shared.b16 {%0,%1,%2,%3}, [%4];"
        : "=r"(r[0]), "=r"(r[1]), "=r"(r[2]), "=r"(r[3]) : "r"(addr));
}
__device__ __forceinline__ void mma_bf16(float d[4], const unsigned a[4],
                                         unsigned b0, unsigned b1) {
    asm volatile("mma.sync.aligned.m16n8k16.row.col.f32.bf16.bf16.f32 "
        "{%0,%1,%2,%3}, {%4,%5,%6,%7}, {%8,%9}, {%0,%1,%2,%3};"
        : "+f"(d[0]), "+f"(d[1]), "+f"(d[2]), "+f"(d[3])
        : "r"(a[0]), "r"(a[1]), "r"(a[2]), "r"(a[3]), "r"(b0), "r"(b1));
}
__device__ __forceinline__ void mma_fp16(float d[4], const unsigned a[4],
                                         unsigned b0, unsigned b1) {
    asm volatile("mma.sync.aligned.m16n8k16.row.col.f32.f16.f16.f32 "
        "{%0,%1,%2,%3}, {%4,%5,%6,%7}, {%8,%9}, {%0,%1,%2,%3};"
        : "+f"(d[0]), "+f"(d[1]), "+f"(d[2]), "+f"(d[3])
        : "r"(a[0]), "r"(a[1]), "r"(a[2]), "r"(a[3]), "r"(b0), "r"(b1));
}
__device__ __forceinline__ unsigned packbf(float lo, float hi) {
    unsigned r;
    asm("cvt.rn.bf16x2.f32 %0, %1, %2;" : "=r"(r) : "f"(hi), "f"(lo));
    return r;
}
__device__ __forceinline__ void splitf(float x, float& h, float& l) {
    __nv_bfloat16 bh = __float2bfloat16_rn(x);
    h = __bfloat162float(bh);
    l = x - h;
}
__device__ __forceinline__ float ex2f(float x) {
    float r;
    asm("ex2.approx.ftz.f32 %0, %1;" : "=f"(r) : "f"(x));
    return r;
}
__device__ __forceinline__ unsigned packh2(float lo, float hi) {
    __half2 h2 = __floats2half2_rn(lo, hi);   // lo -> low half
    return *(unsigned*)&h2;
}
#define CP16(saddr, gptr) \
    asm volatile("cp.async.cg.shared.global [%0], [%1], 16;" :: "r"(saddr), "l"(gptr))
#define CP_COMMIT() asm volatile("cp.async.commit_group;" ::: "memory")
#define CP_WAIT0() asm volatile("cp.async.wait_group 0;" ::: "memory")
#define CP_WAIT1() asm volatile("cp.async.wait_group 1;" ::: "memory")

// ---------------- weight prep: transpose + split ----------------
__global__ void wprep4(const float* __restrict__ W0, const float* __restrict__ W1,
                       const float* __restrict__ W2, const float* __restrict__ W3,
                       __nv_bfloat16* __restrict__ Th, __nv_bfloat16* __restrict__ Tl)
{
    __shared__ float tile[32][33];
    int z = blockIdx.z;
    const float* W = z == 0 ? W0 : z == 1 ? W1 : z == 2 ? W2 : W3;
    __nv_bfloat16* th = Th + (size_t)z * H_ * H_;
    __nv_bfloat16* tl = Tl + (size_t)z * H_ * H_;
    int k0 = blockIdx.x * 32, n0 = blockIdx.y * 32;
    int tx = threadIdx.x, ty = threadIdx.y;
    for (int i = ty; i < 32; i += 8)
        tile[i][tx] = W[(size_t)(k0 + i) * H_ + n0 + tx];
    __syncthreads();
    for (int i = ty; i < 32; i += 8) {
        float v = tile[tx][i];
        float h, l; splitf(v, h, l);
        size_t o = (size_t)(n0 + i) * H_ + k0 + tx;
        th[o] = __float2bfloat16_rn(h);
        tl[o] = __float2bfloat16_rn(l);
    }
}

// ---------------- elementwise split (cross_states) ----------------
__global__ void splitconv(const float* __restrict__ x,
                          __nv_bfloat16* __restrict__ oh, __nv_bfloat16* __restrict__ ol)
{
    int idx = (blockIdx.x * 256 + threadIdx.x) * 4;
    float4 v = *(const float4*)(x + idx);
    float h0,l0,h1,l1,h2,l2,h3,l3;
    splitf(v.x,h0,l0); splitf(v.y,h1,l1); splitf(v.z,h2,l2); splitf(v.w,h3,l3);
    unsigned* ph = (unsigned*)(oh + idx);
    unsigned* pl = (unsigned*)(ol + idx);
    ph[0] = packbf(h0,h1); ph[1] = packbf(h2,h3);
    pl[0] = packbf(l0,l1); pl[1] = packbf(l2,l3);
}

// ---------------- mask int32 -> byte ----------------
__global__ void maskprep(const int* __restrict__ m, unsigned char* __restrict__ o)
{
    size_t i = ((size_t)blockIdx.x * 256 + threadIdx.x);
    const int4* mp = (const int4*)(m + i * 16);
    int4 a = mp[0], b = mp[1], c = mp[2], d = mp[3];
    uint4 r;
    r.x = (a.x!=0) | ((a.y!=0)<<8) | ((a.z!=0)<<16) | ((unsigned)(a.w!=0)<<24);
    r.y = (b.x!=0) | ((b.y!=0)<<8) | ((b.z!=0)<<16) | ((unsigned)(b.w!=0)<<24);
    r.z = (c.x!=0) | ((c.y!=0)<<8) | ((c.z!=0)<<16) | ((unsigned)(c.w!=0)<<24);
    r.w = (d.x!=0) | ((d.y!=0)<<8) | ((d.z!=0)<<16) | ((unsigned)(d.w!=0)<<24);
    *(uint4*)(o + i * 16) = r;
}

// ---------------- LayerNorm -> split bf16 ----------------
__global__ void ln_kernel(const float* __restrict__ x, const float* __restrict__ gam,
                          const float* __restrict__ bet,
                          __nv_bfloat16* __restrict__ oh, __nv_bfloat16* __restrict__ ol)
{
    int row = blockIdx.x;
    int t = threadIdx.x;
    const float* xr = x + (size_t)row * H_;
    float v0 = xr[t], v1 = xr[t+256], v2 = xr[t+512];
    float s  = v0 + v1 + v2;
    float sq = v0*v0 + v1*v1 + v2*v2;
    #pragma unroll
    for (int off = 16; off; off >>= 1) {
        s  += __shfl_xor_sync(~0u, s,  off);
        sq += __shfl_xor_sync(~0u, sq, off);
    }
    __shared__ float rs[8], rq[8];
    int w = t >> 5;
    if ((t & 31) == 0) { rs[w] = s; rq[w] = sq; }
    __syncthreads();
    if (t < 32) {
        float a  = (t < 8) ? rs[t] : 0.f;
        float b2 = (t < 8) ? rq[t] : 0.f;
        #pragma unroll
        for (int off = 4; off; off >>= 1) {
            a  += __shfl_xor_sync(~0u, a,  off);
            b2 += __shfl_xor_sync(~0u, b2, off);
        }
        if (t == 0) { rs[0] = a; rq[0] = b2; }
    }
    __syncthreads();
    float mu  = rs[0] * (1.f / H_);
    float var = rq[0] * (1.f / H_) - mu * mu;
    float r   = rsqrtf(var + 1e-5f);
    size_t base = (size_t)row * H_;
    #pragma unroll
    for (int e = 0; e < 3; e++) {
        int c = t + e * 256;
        float val = ((e==0?v0:e==1?v1:v2) - mu) * r * gam[c] + bet[c];
        float h, l; splitf(val, h, l);
        oh[base + c] = __float2bfloat16_rn(h);
        ol[base + c] = __float2bfloat16_rn(l);
    }
}

// ---------------- GEMM: cp.async 2-stage pipeline, bf16-split mma ----------------
#define GP2 40
#define GPLANE (128*GP2)
#define GSMEM (int)(2*4*GPLANE*sizeof(__nv_bfloat16))   // 81920

__global__ void __launch_bounds__(256, 2) gemm_qkv(
    const __nv_bfloat16* __restrict__ xnh, const __nv_bfloat16* __restrict__ xnl,
    const __nv_bfloat16* __restrict__ crh, const __nv_bfloat16* __restrict__ crl,
    const __nv_bfloat16* __restrict__ wth, const __nv_bfloat16* __restrict__ wtl,
    const float* __restrict__ bq, const float* __restrict__ bk, const float* __restrict__ bv,
    const float* __restrict__ mem,
    const float* __restrict__ gate, const float* __restrict__ gbias,
    const float* __restrict__ dyn,
    __nv_bfloat16* __restrict__ qhp, __nv_bfloat16* __restrict__ qlp,
    __nv_bfloat16* __restrict__ khp, __nv_bfloat16* __restrict__ klp,
    __nv_bfloat16* __restrict__ vhp, __nv_bfloat16* __restrict__ vlp,
    float* __restrict__ Cf, int fused)
{
    extern __shared__ __nv_bfloat16 gsm[];
    int t = threadIdx.x, w = t >> 5, lane = t & 31;
    int wm = w & 1, wn = w >> 1;
    int m0 = blockIdx.x * 128, n0 = blockIdx.y * 128;
    int g = lane >> 2, qd = lane & 3;
    int z = blockIdx.z;

    const __nv_bfloat16 *Ahi, *Alo, *Bhi, *Blo;
    const float *bias, *memadd = nullptr;
    __nv_bfloat16 *Chi = nullptr, *Clo = nullptr;
    int mode;
    bool vhalf = false;
    if (fused) {
        Ahi = xnh; Alo = xnl; Bhi = wth; Blo = wtl;
        bias = bq; mode = 2;
    } else if (z == 0) {
        Ahi = xnh; Alo = xnl; Bhi = wth; Blo = wtl;
        bias = bq; mode = 0; Chi = qhp; Clo = qlp;
    } else if (z == 1) {
        Ahi = crh; Alo = crl;
        Bhi = wth + (size_t)H_*H_; Blo = wtl + (size_t)H_*H_;
        bias = bk; mode = 1; memadd = mem; Chi = khp; Clo = klp;
    } else {
        Ahi = crh; Alo = crl;
        Bhi = wth + 2*(size_t)H_*H_; Blo = wtl + 2*(size_t)H_*H_;
        bias = bv; mode = 1; memadd = mem + (size_t)ROWS*H_; Chi = vhp; Clo = vlp;
        vhalf = true;
    }

    auto load_stage = [&](int k0, int s) {
        #pragma unroll
        for (int p = 0; p < 4; p++) {
            const __nv_bfloat16* src = p == 0 ? Ahi : p == 1 ? Alo : p == 2 ? Bhi : Blo;
            int rbase = (p < 2) ? m0 : n0;
            __nv_bfloat16* dst = gsm + (s*4 + p) * GPLANE;
            #pragma unroll
            for (int i = t; i < 512; i += 256) {
                int r = i >> 2, c = (i & 3) * 8;
                CP16(sa(dst + r*GP2 + c), src + (size_t)(rbase + r) * H_ + k0 + c);
            }
        }
        CP_COMMIT();
    };

    float acc[4][4][4] = {};
    int lr = lane & 15, lc = (lane >> 4) * 8;

    // hoisted stage-0 base addresses; stage offset is a single constant add
    const unsigned aH0 = sa(gsm + 0*GPLANE + (wm*64 + lr)*GP2 + lc);
    const unsigned aL0 = sa(gsm + 1*GPLANE + (wm*64 + lr)*GP2 + lc);
    const unsigned bH0 = sa(gsm + 2*GPLANE + (wn*32 + lr)*GP2 + lc);
    const unsigned bL0 = sa(gsm + 3*GPLANE + (wn*32 + lr)*GP2 + lc);
    const unsigned SOFF = 4*GPLANE*2;

    load_stage(0, 0);
    const int NIT = H_ / 32;           // 24
    for (int j = 0; j < NIT; j++) {
        int s = j & 1;
        if (j + 1 < NIT) { load_stage((j + 1) * 32, s ^ 1); CP_WAIT1(); }
        else             { CP_WAIT0(); }
        __syncthreads();

        unsigned so = s ? SOFF : 0;
        unsigned aH = aH0 + so, aL = aL0 + so, bH = bH0 + so, bL = bL0 + so;

        #pragma unroll
        for (int kh = 0; kh < 2; kh++) {
            unsigned ah[4][4], al[4][4], bh[2][4], bl[2][4];
            #pragma unroll
            for (int mt = 0; mt < 4; mt++) {
                unsigned off = (mt*16*GP2 + kh*16) * 2;
                ldsm4(ah[mt], aH + off);
                ldsm4(al[mt], aL + off);
            }
            #pragma unroll
            for (int ng = 0; ng < 2; ng++) {
                unsigned off = (ng*16*GP2 + kh*16) * 2;
                ldsm4(bh[ng], bH + off);
                ldsm4(bl[ng], bL + off);
            }
            #pragma unroll
            for (int mt = 0; mt < 4; mt++)
                #pragma unroll
                for (int ng = 0; ng < 2; ng++)
                    #pragma unroll
                    for (int tl = 0; tl < 2; tl++) {
                        float* d = acc[mt][ng*2 + tl];
                        mma_bf16(d, ah[mt], bh[ng][tl], bh[ng][tl+2]);
                        mma_bf16(d, ah[mt], bl[ng][tl], bl[ng][tl+2]);
                        mma_bf16(d, al[mt], bh[ng][tl], bh[ng][tl+2]);
                    }
        }
        __syncthreads();
    }

    float gv = 1.f, gb = 0.f;
    if (mode == 2) { gv = gate[0]; gb = gbias[0]; }
    #pragma unroll
    for (int mt = 0; mt < 4; mt++) {
        #pragma unroll
        for (int nt = 0; nt < 4; nt++) {
            int col = n0 + wn*32 + nt*8 + qd*2;
            float2 bvv = *(const float2*)(bias + col);
            #pragma unroll
            for (int rj = 0; rj < 2; rj++) {
                int row = m0 + wm*64 + mt*16 + g + rj*8;
                float x0 = acc[mt][nt][rj*2]   + bvv.x;
                float x1 = acc[mt][nt][rj*2+1] + bvv.y;
                if (mode == 1) {
                    float2 mm = *(const float2*)(memadd + (size_t)row * H_ + col);
                    x0 += 0.5f * mm.x; x1 += 0.5f * mm.y;
                }
                if (mode == 2) {
                    float d = dyn[row];
                    x0 = (x0*gv + gb) * d; x1 = (x1*gv + gb) * d;
                    *(float2*)(Cf + (size_t)row * H_ + col) = make_float2(x0, x1);
                } else if (vhalf) {
                    // fp16 hi/lo split for V
                    __half2 hi2 = __floats2half2_rn(x0, x1);
                    float2 hf = __half22float2(hi2);
                    __half2 lo2 = __floats2half2_rn(x0 - hf.x, x1 - hf.y);
                    size_t o = (size_t)row * H_ + col;
                    *(unsigned*)(Chi + o) = *(unsigned*)&hi2;
                    *(unsigned*)(Clo + o) = *(unsigned*)&lo2;
                } else {
                    float h0,l0,h1,l1;
                    splitf(x0,h0,l0); splitf(x1,h1,l1);
                    size_t o = (size_t)row * H_ + col;
                    *(unsigned*)(Chi + o) = packbf(h0,h1);
                    *(unsigned*)(Clo + o) = packbf(l0,l1);
                }
            }
        }
    }
}

// ---------------- Flash attention ----------------
#define FP 72
#define MPAD 80
#define NKT (S_/64)
// smem: Qh,Ql (64*FP each) | KV 2 stages x 4 planes x 64*FP | mask 2 x 64*MPAD
#define FSMEM (int)((2 + 2*4) * 64 * FP * sizeof(__nv_bfloat16) + 2 * 64 * MPAD)  // 102400

__global__ void __launch_bounds__(128) flash_mma(
    const __nv_bfloat16* __restrict__ qh, const __nv_bfloat16* __restrict__ ql,
    const __nv_bfloat16* __restrict__ kh, const __nv_bfloat16* __restrict__ kl,
    const __nv_bfloat16* __restrict__ vh, const __nv_bfloat16* __restrict__ vl,
    const unsigned char* __restrict__ mask8,
    __nv_bfloat16* __restrict__ aoh, __nv_bfloat16* __restrict__ aol)
{
    extern __shared__ char fsm[];
    __nv_bfloat16* Qh = (__nv_bfloat16*)fsm;
    __nv_bfloat16* Ql = Qh + 64*FP;
    __nv_bfloat16* KV = Ql + 64*FP;
    unsigned char* Ms = (unsigned char*)(KV + 2*4*64*FP);

    int t = threadIdx.x, w = t >> 5, lane = t & 31;
    int g = lane >> 2, qd = lane & 3;
    int q0 = blockIdx.x * 64, h = blockIdx.y, b = blockIdx.z;
    const size_t basec = (size_t)b * S_ * H_ + h * 64;
    const unsigned char* mb8 = mask8 + (size_t)b * S_ * S_;
    const float SCL = 0.125f * 1.44269504f;   // 1/sqrt(HD) * log2(e)

    for (int i = t; i < 512; i += 128) {
        int r = i >> 3, c = (i & 7) * 8;
        size_t gi = basec + (size_t)(q0 + r) * H_ + c;
        *(uint4*)&Qh[r*FP + c] = *(const uint4*)(qh + gi);
        *(uint4*)&Ql[r*FP + c] = *(const uint4*)(ql + gi);
    }

    auto load_stage = [&](int k0, int s) {
        #pragma unroll
        for (int p = 0; p < 4; p++) {
            const __nv_bfloat16* src = p==0 ? kh : p==1 ? kl : p==2 ? vh : vl;
            __nv_bfloat16* dst = KV + (s*4 + p) * 64*FP;
            #pragma unroll
            for (int i = t; i < 512; i += 128) {
                int r = i >> 3, c = (i & 7) * 8;
                CP16(sa(dst + r*FP + c), src + basec + (size_t)(k0 + r) * H_ + c);
            }
        }
        unsigned char* msp = Ms + s * 64*MPAD;
        #pragma unroll
        for (int i = t; i < 256; i += 128) {
            int r = i >> 2, c = (i & 3) * 16;
            CP16(sa(msp + r*MPAD + c), mb8 + (size_t)(q0 + r) * S_ + k0 + c);
        }
        CP_COMMIT();
    };

    load_stage(0, 0);
    __syncthreads();

    int lr = lane & 15, lc = (lane >> 4) * 8;
    unsigned qfh[4][4], qfl[4][4];
    #pragma unroll
    for (int kb = 0; kb < 4; kb++) {
        ldsm4(qfh[kb], sa(&Qh[(w*16 + lr)*FP + lc + kb*16]));
        ldsm4(qfl[kb], sa(&Ql[(w*16 + lr)*FP + lc + kb*16]));
    }

    float mrow[2] = {-CUDART_INF_F, -CUDART_INF_F};
    float lrow_[2] = {0.f, 0.f};
    float oacc[8][4] = {};

    for (int j = 0; j < NKT; j++) {
        int s = j & 1;
        if (j + 1 < NKT) { load_stage((j + 1) * 64, s ^ 1); CP_WAIT1(); }
        else             { CP_WAIT0(); }
        __syncthreads();

        const __nv_bfloat16* Khs = KV + (s*4 + 0) * 64*FP;
        const __nv_bfloat16* Kls = KV + (s*4 + 1) * 64*FP;
        const __nv_bfloat16* Vhs = KV + (s*4 + 2) * 64*FP;
        const __nv_bfloat16* Vls = KV + (s*4 + 3) * 64*FP;
        const unsigned char* msp = Ms + s * 64*MPAD;

        // S = Q K^T (split bf16, 3-term)
        float sreg[8][4] = {};
        #pragma unroll
        for (int kb = 0; kb < 4; kb++) {
            #pragma unroll
            for (int ng = 0; ng < 4; ng++) {
                unsigned b4h[4], b4l[4];
                unsigned off = ((ng*16 + lr)*FP + lc + kb*16) * 2;
                ldsm4(b4h, sa(Khs) + off);
                ldsm4(b4l, sa(Kls) + off);
                #pragma unroll
                for (int tl = 0; tl < 2; tl++) {
                    float* d = sreg[ng*2 + tl];
                    mma_bf16(d, qfh[kb], b4h[tl], b4h[tl+2]);
                    mma_bf16(d, qfh[kb], b4l[tl], b4l[tl+2]);
                    mma_bf16(d, qfl[kb], b4h[tl], b4h[tl+2]);
                }
            }
        }

        // mask + scale (log2 domain)
        #pragma unroll
        for (int nt = 0; nt < 8; nt++)
            #pragma unroll
            for (int jj = 0; jj < 4; jj++) {
                int row = w*16 + g + (jj >> 1) * 8;
                int col = nt*8 + qd*2 + (jj & 1);
                sreg[nt][jj] = msp[row*MPAD + col] ? sreg[nt][jj] * SCL : -CUDART_INF_F;
            }

        // online softmax (base-2)
        #pragma unroll
        for (int rj = 0; rj < 2; rj++) {
            float mx = -CUDART_INF_F;
            #pragma unroll
            for (int nt = 0; nt < 8; nt++)
                mx = fmaxf(mx, fmaxf(sreg[nt][rj*2], sreg[nt][rj*2+1]));
            mx = fmaxf(mx, __shfl_xor_sync(~0u, mx, 1));
            mx = fmaxf(mx, __shfl_xor_sync(~0u, mx, 2));
            float nm = fmaxf(mrow[rj], mx);
            float corr, rsum = 0.f;
            if (nm == -CUDART_INF_F) {
                corr = 1.f;
                #pragma unroll
                for (int nt = 0; nt < 8; nt++) { sreg[nt][rj*2] = 0.f; sreg[nt][rj*2+1] = 0.f; }
            } else {
                corr = ex2f(mrow[rj] - nm);
                #pragma unroll
                for (int nt = 0; nt < 8; nt++) {
                    float p0 = ex2f(sreg[nt][rj*2]   - nm);
                    float p1 = ex2f(sreg[nt][rj*2+1] - nm);
                    sreg[nt][rj*2] = p0; sreg[nt][rj*2+1] = p1;
                    rsum += p0 + p1;
                }
            }
            rsum += __shfl_xor_sync(~0u, rsum, 1);
            rsum += __shfl_xor_sync(~0u, rsum, 2);
            mrow[rj] = nm;
            lrow_[rj] = lrow_[rj] * corr + rsum;
            #pragma unroll
            for (int nt = 0; nt < 8; nt++) {
                oacc[nt][rj*2]   *= corr;
                oacc[nt][rj*2+1] *= corr;
            }
        }

        // pack P -> fp16 A fragments (single precision P)
        unsigned pf[4][4];
        #pragma unroll
        for (int kb = 0; kb < 4; kb++) {
            #pragma unroll
            for (int half = 0; half < 2; half++) {
                int nt = kb*2 + half;
                pf[kb][half*2]   = packh2(sreg[nt][0], sreg[nt][1]);
                pf[kb][half*2+1] = packh2(sreg[nt][2], sreg[nt][3]);
            }
        }

        // O += P V (fp16, 2-term: V hi + V lo)
        #pragma unroll
        for (int kb = 0; kb < 4; kb++) {
            #pragma unroll
            for (int ng = 0; ng < 4; ng++) {
                unsigned v4h[4], v4l[4];
                unsigned off = ((kb*16 + lr)*FP + ng*16 + lc) * 2;
                ldsm4t(v4h, sa(Vhs) + off);
                ldsm4t(v4l, sa(Vls) + off);
                #pragma unroll
                for (int tl = 0; tl < 2; tl++) {
                    float* d = oacc[ng*2 + tl];
                    mma_fp16(d, pf[kb], v4h[tl*2], v4h[tl*2+1]);
                    mma_fp16(d, pf[kb], v4l[tl*2], v4l[tl*2+1]);
                }
            }
        }
        __syncthreads();
    }

    // epilogue -> bf16 hi/lo for out-proj GEMM
    #pragma unroll
    for (int rj = 0; rj < 2; rj++) {
        float inv = lrow_[rj] > 0.f ? 1.f / lrow_[rj] : 0.f;
        int row = q0 + w*16 + g + rj*8;
        #pragma unroll
        for (int nt = 0; nt < 8; nt++) {
            int col = nt*8 + qd*2;
            float x0 = oacc[nt][rj*2] * inv, x1 = oacc[nt][rj*2+1] * inv;
            float h0,l0,h1,l1;
            splitf(x0,h0,l0); splitf(x1,h1,l1);
            size_t o = basec + (size_t)row * H_ + col;
            *(unsigned*)(aoh + o) = packbf(h0,h1);
            *(unsigned*)(aol + o) = packbf(l0,l1);
        }
    }
}

// ---------------- launch ----------------
extern "C" void kernel_launch(void* const* d_in, const int* in_sizes, int n_in,
                              void* d_out, int out_size)
{
    const float* hidden = (const float*)d_in[0];
    const float* cross  = (const float*)d_in[1];
    const int*   amask  = (const int*)  d_in[2];
    const float* mem    = (const float*)d_in[3];
    const float* dyn    = (const float*)d_in[4];
    const float* Wq = (const float*)d_in[5];  const float* bq = (const float*)d_in[6];
    const float* Wk = (const float*)d_in[7];  const float* bk = (const float*)d_in[8];
    const float* Wv = (const float*)d_in[9];  const float* bv = (const float*)d_in[10];
    const float* Wo = (const float*)d_in[11]; const float* bo = (const float*)d_in[12];
    const float* gate  = (const float*)d_in[13];
    const float* gbias = (const float*)d_in[14];
    const float* lng   = (const float*)d_in[15];
    const float* lnb   = (const float*)d_in[16];
    float* out = (float*)d_out;

    __nv_bfloat16 *xnh,*xnl,*crh,*crl,*qhp,*qlp,*khp,*klp,*vhp,*vlp,*aoh,*aol,*wth,*wtl;
    unsigned char* m8;
    cudaGetSymbolAddress((void**)&xnh, g_xn_hi); cudaGetSymbolAddress((void**)&xnl, g_xn_lo);
    cudaGetSymbolAddress((void**)&crh, g_cr_hi); cudaGetSymbolAddress((void**)&crl, g_cr_lo);
    cudaGetSymbolAddress((void**)&qhp, g_q_hi);  cudaGetSymbolAddress((void**)&qlp, g_q_lo);
    cudaGetSymbolAddress((void**)&khp, g_k_hi);  cudaGetSymbolAddress((void**)&klp, g_k_lo);
    cudaGetSymbolAddress((void**)&vhp, g_v_hi);  cudaGetSymbolAddress((void**)&vlp, g_v_lo);
    cudaGetSymbolAddress((void**)&aoh, g_ao_hi); cudaGetSymbolAddress((void**)&aol, g_ao_lo);
    cudaGetSymbolAddress((void**)&wth, g_wt_hi); cudaGetSymbolAddress((void**)&wtl, g_wt_lo);
    cudaGetSymbolAddress((void**)&m8,  g_mask8);

    cudaFuncSetAttribute(gemm_qkv, cudaFuncAttributeMaxDynamicSharedMemorySize, GSMEM);
    cudaFuncSetAttribute(flash_mma, cudaFuncAttributeMaxDynamicSharedMemorySize, FSMEM);

    wprep4<<<dim3(H_/32, H_/32, 4), dim3(32,8)>>>(Wq, Wk, Wv, Wo, wth, wtl);
    ln_kernel<<<ROWS, 256>>>(hidden, lng, lnb, xnh, xnl);
    splitconv<<<ROWS*H_/1024, 256>>>(cross, crh, crl);
    maskprep<<<(size_t)B_*S_*S_/16/256, 256>>>(amask, m8);

    gemm_qkv<<<dim3(ROWS/128, H_/128, 3), 256, GSMEM>>>(
        xnh, xnl, crh, crl, wth, wtl, bq, bk, bv, mem,
        nullptr, nullptr, nullptr,
        qhp, qlp, khp, klp, vhp, vlp, nullptr, 0);

    flash_mma<<<dim3(S_/64, NH_, B_), 128, FSMEM>>>(qhp, qlp, khp, klp, vhp, vlp, m8, aoh, aol);

    gemm_qkv<<<dim3(ROWS/128, H_/128, 1), 256, GSMEM>>>(
        aoh, aol, nullptr, nullptr, wth + 3*(size_t)H_*H_, wtl + 3*(size_t)H_*H_,
        bo, nullptr, nullptr, nullptr,
        gate, gbias, dyn,
        nullptr, nullptr, nullptr, nullptr, nullptr, nullptr, out, 1);
}

// round 8
// speedup vs baseline: 3.4317x; 1.1734x over previous
#include <cuda_runtime.h>
#include <cuda_bf16.h>
#include <cuda_fp16.h>
#include <math_constants.h>
#include <cstdint>

#define B_   2
#define S_   2048
#define H_   768
#define NH_  12
#define HD_  64
#define ROWS (B_*S_)          // 4096

// ---------------- scratch ----------------
__device__ __align__(256) __nv_bfloat16 g_xn_hi[ROWS*H_];
__device__ __align__(256) __nv_bfloat16 g_xn_lo[ROWS*H_];
__device__ __align__(256) __nv_bfloat16 g_cr_hi[ROWS*H_];
__device__ __align__(256) __nv_bfloat16 g_cr_lo[ROWS*H_];
__device__ __align__(256) __half        g_q16  [ROWS*H_];   // Q single fp16
__device__ __align__(256) __half        g_k_hi [ROWS*H_];   // K fp16 hi
__device__ __align__(256) __half        g_k_lo [ROWS*H_];   // K fp16 lo
__device__ __align__(256) __half        g_v16  [ROWS*H_];   // V single fp16
__device__ __align__(256) __nv_bfloat16 g_ao_hi[ROWS*H_];
__device__ __align__(256) __nv_bfloat16 g_ao_lo[ROWS*H_];
__device__ __align__(256) __nv_bfloat16 g_wt_hi[4*H_*H_];
__device__ __align__(256) __nv_bfloat16 g_wt_lo[4*H_*H_];
__device__ __align__(256) unsigned char g_mask8[(size_t)B_*S_*S_];

// ---------------- helpers ----------------
__device__ __forceinline__ unsigned sa(const void* p) {
    return (unsigned)__cvta_generic_to_shared(p);
}
__device__ __forceinline__ void ldsm4(unsigned r[4], unsigned addr) {
    asm volatile("ldmatrix.sync.aligned.m8n8.x4.shared.b16 {%0,%1,%2,%3}, [%4];"
        : "=r"(r[0]), "=r"(r[1]), "=r"(r[2]), "=r"(r[3]) : "r"(addr));
}
__device__ __forceinline__ void ldsm4t(unsigned r[4], unsigned addr) {
    asm volatile("ldmatrix.sync.aligned.m8n8.x4.trans.shared.b16 {%0,%1,%2,%3}, [%4];"
        : "=r"(r[0]), "=r"(r[1]), "=r"(r[2]), "=r"(r[3]) : "r"(addr));
}
__device__ __forceinline__ void mma_bf16(float d[4], const unsigned a[4],
                                         unsigned b0, unsigned b1) {
    asm volatile("mma.sync.aligned.m16n8k16.row.col.f32.bf16.bf16.f32 "
        "{%0,%1,%2,%3}, {%4,%5,%6,%7}, {%8,%9}, {%0,%1,%2,%3};"
        : "+f"(d[0]), "+f"(d[1]), "+f"(d[2]), "+f"(d[3])
        : "r"(a[0]), "r"(a[1]), "r"(a[2]), "r"(a[3]), "r"(b0), "r"(b1));
}
__device__ __forceinline__ void mma_fp16(float d[4], const unsigned a[4],
                                         unsigned b0, unsigned b1) {
    asm volatile("mma.sync.aligned.m16n8k16.row.col.f32.f16.f16.f32 "
        "{%0,%1,%2,%3}, {%4,%5,%6,%7}, {%8,%9}, {%0,%1,%2,%3};"
        : "+f"(d[0]), "+f"(d[1]), "+f"(d[2]), "+f"(d[3])
        : "r"(a[0]), "r"(a[1]), "r"(a[2]), "r"(a[3]), "r"(b0), "r"(b1));
}
__device__ __forceinline__ unsigned packbf(float lo, float hi) {
    unsigned r;
    asm("cvt.rn.bf16x2.f32 %0, %1, %2;" : "=r"(r) : "f"(hi), "f"(lo));
    return r;
}
__device__ __forceinline__ void splitf(float x, float& h, float& l) {
    __nv_bfloat16 bh = __float2bfloat16_rn(x);
    h = __bfloat162float(bh);
    l = x - h;
}
__device__ __forceinline__ float ex2f(float x) {
    float r;
    asm("ex2.approx.ftz.f32 %0, %1;" : "=f"(r) : "f"(x));
    return r;
}
__device__ __forceinline__ unsigned packh2(float lo, float hi) {
    __half2 h2 = __floats2half2_rn(lo, hi);
    return *(unsigned*)&h2;
}
#define CP16(saddr, gptr) \
    asm volatile("cp.async.cg.shared.global [%0], [%1], 16;" :: "r"(saddr), "l"(gptr))
#define CP_COMMIT() asm volatile("cp.async.commit_group;" ::: "memory")
#define CP_WAIT0() asm volatile("cp.async.wait_group 0;" ::: "memory")
#define CP_WAIT1() asm volatile("cp.async.wait_group 1;" ::: "memory")

// ---------------- weight prep ----------------
__global__ void wprep4(const float* __restrict__ W0, const float* __restrict__ W1,
                       const float* __restrict__ W2, const float* __restrict__ W3,
                       __nv_bfloat16* __restrict__ Th, __nv_bfloat16* __restrict__ Tl)
{
    __shared__ float tile[32][33];
    int z = blockIdx.z;
    const float* W = z == 0 ? W0 : z == 1 ? W1 : z == 2 ? W2 : W3;
    __nv_bfloat16* th = Th + (size_t)z * H_ * H_;
    __nv_bfloat16* tl = Tl + (size_t)z * H_ * H_;
    int k0 = blockIdx.x * 32, n0 = blockIdx.y * 32;
    int tx = threadIdx.x, ty = threadIdx.y;
    for (int i = ty; i < 32; i += 8)
        tile[i][tx] = W[(size_t)(k0 + i) * H_ + n0 + tx];
    __syncthreads();
    for (int i = ty; i < 32; i += 8) {
        float v = tile[tx][i];
        float h, l; splitf(v, h, l);
        size_t o = (size_t)(n0 + i) * H_ + k0 + tx;
        th[o] = __float2bfloat16_rn(h);
        tl[o] = __float2bfloat16_rn(l);
    }
}

// ---------------- elementwise split (cross_states) ----------------
__global__ void splitconv(const float* __restrict__ x,
                          __nv_bfloat16* __restrict__ oh, __nv_bfloat16* __restrict__ ol)
{
    int idx = (blockIdx.x * 256 + threadIdx.x) * 4;
    float4 v = *(const float4*)(x + idx);
    float h0,l0,h1,l1,h2,l2,h3,l3;
    splitf(v.x,h0,l0); splitf(v.y,h1,l1); splitf(v.z,h2,l2); splitf(v.w,h3,l3);
    unsigned* ph = (unsigned*)(oh + idx);
    unsigned* pl = (unsigned*)(ol + idx);
    ph[0] = packbf(h0,h1); ph[1] = packbf(h2,h3);
    pl[0] = packbf(l0,l1); pl[1] = packbf(l2,l3);
}

// ---------------- mask int32 -> byte ----------------
__global__ void maskprep(const int* __restrict__ m, unsigned char* __restrict__ o)
{
    size_t i = ((size_t)blockIdx.x * 256 + threadIdx.x);
    const int4* mp = (const int4*)(m + i * 16);
    int4 a = mp[0], b = mp[1], c = mp[2], d = mp[3];
    uint4 r;
    r.x = (a.x!=0) | ((a.y!=0)<<8) | ((a.z!=0)<<16) | ((unsigned)(a.w!=0)<<24);
    r.y = (b.x!=0) | ((b.y!=0)<<8) | ((b.z!=0)<<16) | ((unsigned)(b.w!=0)<<24);
    r.z = (c.x!=0) | ((c.y!=0)<<8) | ((c.z!=0)<<16) | ((unsigned)(c.w!=0)<<24);
    r.w = (d.x!=0) | ((d.y!=0)<<8) | ((d.z!=0)<<16) | ((unsigned)(d.w!=0)<<24);
    *(uint4*)(o + i * 16) = r;
}

// ---------------- LayerNorm -> split bf16 ----------------
__global__ void ln_kernel(const float* __restrict__ x, const float* __restrict__ gam,
                          const float* __restrict__ bet,
                          __nv_bfloat16* __restrict__ oh, __nv_bfloat16* __restrict__ ol)
{
    int row = blockIdx.x;
    int t = threadIdx.x;
    const float* xr = x + (size_t)row * H_;
    float v0 = xr[t], v1 = xr[t+256], v2 = xr[t+512];
    float s  = v0 + v1 + v2;
    float sq = v0*v0 + v1*v1 + v2*v2;
    #pragma unroll
    for (int off = 16; off; off >>= 1) {
        s  += __shfl_xor_sync(~0u, s,  off);
        sq += __shfl_xor_sync(~0u, sq, off);
    }
    __shared__ float rs[8], rq[8];
    int w = t >> 5;
    if ((t & 31) == 0) { rs[w] = s; rq[w] = sq; }
    __syncthreads();
    if (t < 32) {
        float a  = (t < 8) ? rs[t] : 0.f;
        float b2 = (t < 8) ? rq[t] : 0.f;
        #pragma unroll
        for (int off = 4; off; off >>= 1) {
            a  += __shfl_xor_sync(~0u, a,  off);
            b2 += __shfl_xor_sync(~0u, b2, off);
        }
        if (t == 0) { rs[0] = a; rq[0] = b2; }
    }
    __syncthreads();
    float mu  = rs[0] * (1.f / H_);
    float var = rq[0] * (1.f / H_) - mu * mu;
    float r   = rsqrtf(var + 1e-5f);
    size_t base = (size_t)row * H_;
    #pragma unroll
    for (int e = 0; e < 3; e++) {
        int c = t + e * 256;
        float val = ((e==0?v0:e==1?v1:v2) - mu) * r * gam[c] + bet[c];
        float h, l; splitf(val, h, l);
        oh[base + c] = __float2bfloat16_rn(h);
        ol[base + c] = __float2bfloat16_rn(l);
    }
}

// ---------------- GEMM: cp.async 2-stage pipeline, bf16-split mma ----------------
// output formats: 1 = fp16 hi/lo pair (K), 2 = fp16 single (Q,V), 3 = float (out-proj)
#define GP2 40
#define GPLANE (128*GP2)
#define GSMEM (int)(2*4*GPLANE*sizeof(__nv_bfloat16))   // 81920

__global__ void __launch_bounds__(256, 2) gemm_qkv(
    const __nv_bfloat16* __restrict__ xnh, const __nv_bfloat16* __restrict__ xnl,
    const __nv_bfloat16* __restrict__ crh, const __nv_bfloat16* __restrict__ crl,
    const __nv_bfloat16* __restrict__ wth, const __nv_bfloat16* __restrict__ wtl,
    const float* __restrict__ bq, const float* __restrict__ bk, const float* __restrict__ bv,
    const float* __restrict__ mem,
    const float* __restrict__ gate, const float* __restrict__ gbias,
    const float* __restrict__ dyn,
    __half* __restrict__ q16, __half* __restrict__ khp, __half* __restrict__ klp,
    __half* __restrict__ v16,
    float* __restrict__ Cf, int fused)
{
    extern __shared__ __nv_bfloat16 gsm[];
    int t = threadIdx.x, w = t >> 5, lane = t & 31;
    int wm = w & 1, wn = w >> 1;
    int m0 = blockIdx.x * 128, n0 = blockIdx.y * 128;
    int g = lane >> 2, qd = lane & 3;
    int z = blockIdx.z;

    const __nv_bfloat16 *Ahi, *Alo, *Bhi, *Blo;
    const float *bias, *memadd = nullptr;
    __half *Co = nullptr, *Co2 = nullptr;
    int mode, ofmt;
    if (fused) {
        Ahi = xnh; Alo = xnl; Bhi = wth; Blo = wtl;
        bias = bq; mode = 2; ofmt = 3;
    } else if (z == 0) {
        Ahi = xnh; Alo = xnl; Bhi = wth; Blo = wtl;
        bias = bq; mode = 0; ofmt = 2; Co = q16;
    } else if (z == 1) {
        Ahi = crh; Alo = crl;
        Bhi = wth + (size_t)H_*H_; Blo = wtl + (size_t)H_*H_;
        bias = bk; mode = 1; memadd = mem; ofmt = 1; Co = khp; Co2 = klp;
    } else {
        Ahi = crh; Alo = crl;
        Bhi = wth + 2*(size_t)H_*H_; Blo = wtl + 2*(size_t)H_*H_;
        bias = bv; mode = 1; memadd = mem + (size_t)ROWS*H_; ofmt = 2; Co = v16;
    }

    auto load_stage = [&](int k0, int s) {
        #pragma unroll
        for (int p = 0; p < 4; p++) {
            const __nv_bfloat16* src = p == 0 ? Ahi : p == 1 ? Alo : p == 2 ? Bhi : Blo;
            int rbase = (p < 2) ? m0 : n0;
            __nv_bfloat16* dst = gsm + (s*4 + p) * GPLANE;
            #pragma unroll
            for (int i = t; i < 512; i += 256) {
                int r = i >> 2, c = (i & 3) * 8;
                CP16(sa(dst + r*GP2 + c), src + (size_t)(rbase + r) * H_ + k0 + c);
            }
        }
        CP_COMMIT();
    };

    float acc[4][4][4] = {};
    int lr = lane & 15, lc = (lane >> 4) * 8;

    const unsigned aH0 = sa(gsm + 0*GPLANE + (wm*64 + lr)*GP2 + lc);
    const unsigned aL0 = sa(gsm + 1*GPLANE + (wm*64 + lr)*GP2 + lc);
    const unsigned bH0 = sa(gsm + 2*GPLANE + (wn*32 + lr)*GP2 + lc);
    const unsigned bL0 = sa(gsm + 3*GPLANE + (wn*32 + lr)*GP2 + lc);
    const unsigned SOFF = 4*GPLANE*2;

    load_stage(0, 0);
    const int NIT = H_ / 32;
    for (int j = 0; j < NIT; j++) {
        int s = j & 1;
        if (j + 1 < NIT) { load_stage((j + 1) * 32, s ^ 1); CP_WAIT1(); }
        else             { CP_WAIT0(); }
        __syncthreads();

        unsigned so = s ? SOFF : 0;
        unsigned aH = aH0 + so, aL = aL0 + so, bH = bH0 + so, bL = bL0 + so;

        #pragma unroll
        for (int kh = 0; kh < 2; kh++) {
            unsigned ah[4][4], al[4][4], bh[2][4], bl[2][4];
            #pragma unroll
            for (int mt = 0; mt < 4; mt++) {
                unsigned off = (mt*16*GP2 + kh*16) * 2;
                ldsm4(ah[mt], aH + off);
                ldsm4(al[mt], aL + off);
            }
            #pragma unroll
            for (int ng = 0; ng < 2; ng++) {
                unsigned off = (ng*16*GP2 + kh*16) * 2;
                ldsm4(bh[ng], bH + off);
                ldsm4(bl[ng], bL + off);
            }
            #pragma unroll
            for (int mt = 0; mt < 4; mt++)
                #pragma unroll
                for (int ng = 0; ng < 2; ng++)
                    #pragma unroll
                    for (int tl = 0; tl < 2; tl++) {
                        float* d = acc[mt][ng*2 + tl];
                        mma_bf16(d, ah[mt], bh[ng][tl], bh[ng][tl+2]);
                        mma_bf16(d, ah[mt], bl[ng][tl], bl[ng][tl+2]);
                        mma_bf16(d, al[mt], bh[ng][tl], bh[ng][tl+2]);
                    }
        }
        __syncthreads();
    }

    float gv = 1.f, gb = 0.f;
    if (mode == 2) { gv = gate[0]; gb = gbias[0]; }
    #pragma unroll
    for (int mt = 0; mt < 4; mt++) {
        #pragma unroll
        for (int nt = 0; nt < 4; nt++) {
            int col = n0 + wn*32 + nt*8 + qd*2;
            float2 bvv = *(const float2*)(bias + col);
            #pragma unroll
            for (int rj = 0; rj < 2; rj++) {
                int row = m0 + wm*64 + mt*16 + g + rj*8;
                float x0 = acc[mt][nt][rj*2]   + bvv.x;
                float x1 = acc[mt][nt][rj*2+1] + bvv.y;
                if (mode == 1) {
                    float2 mm = *(const float2*)(memadd + (size_t)row * H_ + col);
                    x0 += 0.5f * mm.x; x1 += 0.5f * mm.y;
                }
                size_t o = (size_t)row * H_ + col;
                if (ofmt == 3) {
                    float d = dyn[row];
                    x0 = (x0*gv + gb) * d; x1 = (x1*gv + gb) * d;
                    *(float2*)(Cf + o) = make_float2(x0, x1);
                } else if (ofmt == 2) {
                    __half2 h2 = __floats2half2_rn(x0, x1);
                    *(unsigned*)(Co + o) = *(unsigned*)&h2;
                } else {
                    __half2 hi2 = __floats2half2_rn(x0, x1);
                    float2 hf = __half22float2(hi2);
                    __half2 lo2 = __floats2half2_rn(x0 - hf.x, x1 - hf.y);
                    *(unsigned*)(Co  + o) = *(unsigned*)&hi2;
                    *(unsigned*)(Co2 + o) = *(unsigned*)&lo2;
                }
            }
        }
    }
}

// ---------------- Flash attention: Q fp16, K fp16 hi/lo, V fp16 ----------------
#define FP 72
#define MPAD 80
#define NKT (S_/64)
// smem: Q (1 plane) | KV 2 stages x 3 planes (Kh,Kl,V) | mask 2 x 64*MPAD
#define FSMEM (int)((1 + 2*3) * 64 * FP * 2 + 2 * 64 * MPAD)   // 74752

__global__ void __launch_bounds__(128) flash_mma(
    const __half* __restrict__ q16,
    const __half* __restrict__ kh, const __half* __restrict__ kl,
    const __half* __restrict__ v16,
    const unsigned char* __restrict__ mask8,
    __nv_bfloat16* __restrict__ aoh, __nv_bfloat16* __restrict__ aol)
{
    extern __shared__ char fsm[];
    __half* Qs = (__half*)fsm;
    __half* KV = Qs + 64*FP;
    unsigned char* Ms = (unsigned char*)(KV + 2*3*64*FP);

    int t = threadIdx.x, w = t >> 5, lane = t & 31;
    int g = lane >> 2, qd = lane & 3;
    int q0 = blockIdx.x * 64, h = blockIdx.y, b = blockIdx.z;
    const size_t basec = (size_t)b * S_ * H_ + h * 64;
    const unsigned char* mb8 = mask8 + (size_t)b * S_ * S_;
    const float SCL = 0.125f * 1.44269504f;

    for (int i = t; i < 512; i += 128) {
        int r = i >> 3, c = (i & 7) * 8;
        *(uint4*)&Qs[r*FP + c] = *(const uint4*)(q16 + basec + (size_t)(q0 + r) * H_ + c);
    }

    auto load_stage = [&](int k0, int s) {
        #pragma unroll
        for (int p = 0; p < 3; p++) {
            const __half* src = p==0 ? kh : p==1 ? kl : v16;
            __half* dst = KV + (s*3 + p) * 64*FP;
            #pragma unroll
            for (int i = t; i < 512; i += 128) {
                int r = i >> 3, c = (i & 7) * 8;
                CP16(sa(dst + r*FP + c), src + basec + (size_t)(k0 + r) * H_ + c);
            }
        }
        unsigned char* msp = Ms + s * 64*MPAD;
        #pragma unroll
        for (int i = t; i < 256; i += 128) {
            int r = i >> 2, c = (i & 3) * 16;
            CP16(sa(msp + r*MPAD + c), mb8 + (size_t)(q0 + r) * S_ + k0 + c);
        }
        CP_COMMIT();
    };

    load_stage(0, 0);
    __syncthreads();

    int lr = lane & 15, lc = (lane >> 4) * 8;
    unsigned qf[4][4];
    #pragma unroll
    for (int kb = 0; kb < 4; kb++)
        ldsm4(qf[kb], sa(&Qs[(w*16 + lr)*FP + lc + kb*16]));

    float mrow[2] = {-CUDART_INF_F, -CUDART_INF_F};
    float lrow_[2] = {0.f, 0.f};
    float oacc[8][4] = {};

    for (int j = 0; j < NKT; j++) {
        int s = j & 1;
        if (j + 1 < NKT) { load_stage((j + 1) * 64, s ^ 1); CP_WAIT1(); }
        else             { CP_WAIT0(); }
        __syncthreads();

        const __half* Khs = KV + (s*3 + 0) * 64*FP;
        const __half* Kls = KV + (s*3 + 1) * 64*FP;
        const __half* Vs  = KV + (s*3 + 2) * 64*FP;
        const unsigned char* msp = Ms + s * 64*MPAD;

        // S = Q K^T  (fp16: Q*Kh + Q*Kl)
        float sreg[8][4] = {};
        #pragma unroll
        for (int kb = 0; kb < 4; kb++) {
            #pragma unroll
            for (int ng = 0; ng < 4; ng++) {
                unsigned b4h[4], b4l[4];
                unsigned off = ((ng*16 + lr)*FP + lc + kb*16) * 2;
                ldsm4(b4h, sa(Khs) + off);
                ldsm4(b4l, sa(Kls) + off);
                #pragma unroll
                for (int tl = 0; tl < 2; tl++) {
                    float* d = sreg[ng*2 + tl];
                    mma_fp16(d, qf[kb], b4h[tl], b4h[tl+2]);
                    mma_fp16(d, qf[kb], b4l[tl], b4l[tl+2]);
                }
            }
        }

        // mask + scale (log2 domain)
        #pragma unroll
        for (int nt = 0; nt < 8; nt++)
            #pragma unroll
            for (int jj = 0; jj < 4; jj++) {
                int row = w*16 + g + (jj >> 1) * 8;
                int col = nt*8 + qd*2 + (jj & 1);
                sreg[nt][jj] = msp[row*MPAD + col] ? sreg[nt][jj] * SCL : -CUDART_INF_F;
            }

        // online softmax (base-2)
        #pragma unroll
        for (int rj = 0; rj < 2; rj++) {
            float mx = -CUDART_INF_F;
            #pragma unroll
            for (int nt = 0; nt < 8; nt++)
                mx = fmaxf(mx, fmaxf(sreg[nt][rj*2], sreg[nt][rj*2+1]));
            mx = fmaxf(mx, __shfl_xor_sync(~0u, mx, 1));
            mx = fmaxf(mx, __shfl_xor_sync(~0u, mx, 2));
            float nm = fmaxf(mrow[rj], mx);
            float corr, rsum = 0.f;
            if (nm == -CUDART_INF_F) {
                corr = 1.f;
                #pragma unroll
                for (int nt = 0; nt < 8; nt++) { sreg[nt][rj*2] = 0.f; sreg[nt][rj*2+1] = 0.f; }
            } else {
                corr = ex2f(mrow[rj] - nm);
                #pragma unroll
                for (int nt = 0; nt < 8; nt++) {
                    float p0 = ex2f(sreg[nt][rj*2]   - nm);
                    float p1 = ex2f(sreg[nt][rj*2+1] - nm);
                    sreg[nt][rj*2] = p0; sreg[nt][rj*2+1] = p1;
                    rsum += p0 + p1;
                }
            }
            rsum += __shfl_xor_sync(~0u, rsum, 1);
            rsum += __shfl_xor_sync(~0u, rsum, 2);
            mrow[rj] = nm;
            lrow_[rj] = lrow_[rj] * corr + rsum;
            #pragma unroll
            for (int nt = 0; nt < 8; nt++) {
                oacc[nt][rj*2]   *= corr;
                oacc[nt][rj*2+1] *= corr;
            }
        }

        // pack P -> fp16 A fragments
        unsigned pf[4][4];
        #pragma unroll
        for (int kb = 0; kb < 4; kb++) {
            #pragma unroll
            for (int half = 0; half < 2; half++) {
                int nt = kb*2 + half;
                pf[kb][half*2]   = packh2(sreg[nt][0], sreg[nt][1]);
                pf[kb][half*2+1] = packh2(sreg[nt][2], sreg[nt][3]);
            }
        }

        // O += P V (fp16 single)
        #pragma unroll
        for (int kb = 0; kb < 4; kb++) {
            #pragma unroll
            for (int ng = 0; ng < 4; ng++) {
                unsigned v4[4];
                unsigned off = ((kb*16 + lr)*FP + ng*16 + lc) * 2;
                ldsm4t(v4, sa(Vs) + off);
                #pragma unroll
                for (int tl = 0; tl < 2; tl++)
                    mma_fp16(oacc[ng*2 + tl], pf[kb], v4[tl*2], v4[tl*2+1]);
            }
        }
        __syncthreads();
    }

    // epilogue -> bf16 hi/lo for out-proj GEMM
    #pragma unroll
    for (int rj = 0; rj < 2; rj++) {
        float inv = lrow_[rj] > 0.f ? 1.f / lrow_[rj] : 0.f;
        int row = q0 + w*16 + g + rj*8;
        #pragma unroll
        for (int nt = 0; nt < 8; nt++) {
            int col = nt*8 + qd*2;
            float x0 = oacc[nt][rj*2] * inv, x1 = oacc[nt][rj*2+1] * inv;
            float h0,l0,h1,l1;
            splitf(x0,h0,l0); splitf(x1,h1,l1);
            size_t o = basec + (size_t)row * H_ + col;
            *(unsigned*)(aoh + o) = packbf(h0,h1);
            *(unsigned*)(aol + o) = packbf(l0,l1);
        }
    }
}

// ---------------- launch ----------------
extern "C" void kernel_launch(void* const* d_in, const int* in_sizes, int n_in,
                              void* d_out, int out_size)
{
    const float* hidden = (const float*)d_in[0];
    const float* cross  = (const float*)d_in[1];
    const int*   amask  = (const int*)  d_in[2];
    const float* mem    = (const float*)d_in[3];
    const float* dyn    = (const float*)d_in[4];
    const float* Wq = (const float*)d_in[5];  const float* bq = (const float*)d_in[6];
    const float* Wk = (const float*)d_in[7];  const float* bk = (const float*)d_in[8];
    const float* Wv = (const float*)d_in[9];  const float* bv = (const float*)d_in[10];
    const float* Wo = (const float*)d_in[11]; const float* bo = (const float*)d_in[12];
    const float* gate  = (const float*)d_in[13];
    const float* gbias = (const float*)d_in[14];
    const float* lng   = (const float*)d_in[15];
    const float* lnb   = (const float*)d_in[16];
    float* out = (float*)d_out;

    __nv_bfloat16 *xnh,*xnl,*crh,*crl,*aoh,*aol,*wth,*wtl;
    __half *q16,*khp,*klp,*v16;
    unsigned char* m8;
    cudaGetSymbolAddress((void**)&xnh, g_xn_hi); cudaGetSymbolAddress((void**)&xnl, g_xn_lo);
    cudaGetSymbolAddress((void**)&crh, g_cr_hi); cudaGetSymbolAddress((void**)&crl, g_cr_lo);
    cudaGetSymbolAddress((void**)&q16, g_q16);
    cudaGetSymbolAddress((void**)&khp, g_k_hi);  cudaGetSymbolAddress((void**)&klp, g_k_lo);
    cudaGetSymbolAddress((void**)&v16, g_v16);
    cudaGetSymbolAddress((void**)&aoh, g_ao_hi); cudaGetSymbolAddress((void**)&aol, g_ao_lo);
    cudaGetSymbolAddress((void**)&wth, g_wt_hi); cudaGetSymbolAddress((void**)&wtl, g_wt_lo);
    cudaGetSymbolAddress((void**)&m8,  g_mask8);

    cudaFuncSetAttribute(gemm_qkv, cudaFuncAttributeMaxDynamicSharedMemorySize, GSMEM);
    cudaFuncSetAttribute(flash_mma, cudaFuncAttributeMaxDynamicSharedMemorySize, FSMEM);

    wprep4<<<dim3(H_/32, H_/32, 4), dim3(32,8)>>>(Wq, Wk, Wv, Wo, wth, wtl);
    ln_kernel<<<ROWS, 256>>>(hidden, lng, lnb, xnh, xnl);
    splitconv<<<ROWS*H_/1024, 256>>>(cross, crh, crl);
    maskprep<<<(size_t)B_*S_*S_/16/256, 256>>>(amask, m8);

    gemm_qkv<<<dim3(ROWS/128, H_/128, 3), 256, GSMEM>>>(
        xnh, xnl, crh, crl, wth, wtl, bq, bk, bv, mem,
        nullptr, nullptr, nullptr,
        q16, khp, klp, v16, nullptr, 0);

    flash_mma<<<dim3(S_/64, NH_, B_), 128, FSMEM>>>(q16, khp, klp, v16, m8, aoh, aol);

    gemm_qkv<<<dim3(ROWS/128, H_/128, 1), 256, GSMEM>>>(
        aoh, aol, nullptr, nullptr, wth + 3*(size_t)H_*H_, wtl + 3*(size_t)H_*H_,
        bo, nullptr, nullptr, nullptr,
        gate, gbias, dyn,
        nullptr, nullptr, nullptr, nullptr, out, 1);
}

// round 11
// speedup vs baseline: 4.8480x; 1.4127x over previous
#include <cuda_runtime.h>
#include <cuda_bf16.h>
#include <cuda_fp16.h>
#include <math_constants.h>
#include <cstdint>

#define B_   2
#define S_   2048
#define H_   768
#define NH_  12
#define HD_  64
#define ROWS (B_*S_)          // 4096

// ---------------- scratch ----------------
__device__ __align__(256) __half g_xn16[ROWS*H_];
__device__ __align__(256) __half g_cr16[ROWS*H_];
__device__ __align__(256) __half g_q16 [ROWS*H_];
__device__ __align__(256) __half g_k16 [ROWS*H_];
__device__ __align__(256) __half g_v16 [ROWS*H_];
__device__ __align__(256) __half g_ao16[ROWS*H_];
__device__ __align__(256) __half g_wt_hi[4*H_*H_];
__device__ __align__(256) __half g_wt_lo[4*H_*H_];
__device__ __align__(256) unsigned char g_mask8[(size_t)B_*S_*S_];

// ---------------- helpers ----------------
__device__ __forceinline__ unsigned sa(const void* p) {
    return (unsigned)__cvta_generic_to_shared(p);
}
__device__ __forceinline__ void ldsm4(unsigned r[4], unsigned addr) {
    asm volatile("ldmatrix.sync.aligned.m8n8.x4.shared.b16 {%0,%1,%2,%3}, [%4];"
        : "=r"(r[0]), "=r"(r[1]), "=r"(r[2]), "=r"(r[3]) : "r"(addr));
}
__device__ __forceinline__ void ldsm4t(unsigned r[4], unsigned addr) {
    asm volatile("ldmatrix.sync.aligned.m8n8.x4.trans.shared.b16 {%0,%1,%2,%3}, [%4];"
        : "=r"(r[0]), "=r"(r[1]), "=r"(r[2]), "=r"(r[3]) : "r"(addr));
}
__device__ __forceinline__ void mma_fp16(float d[4], const unsigned a[4],
                                         unsigned b0, unsigned b1) {
    asm volatile("mma.sync.aligned.m16n8k16.row.col.f32.f16.f16.f32 "
        "{%0,%1,%2,%3}, {%4,%5,%6,%7}, {%8,%9}, {%0,%1,%2,%3};"
        : "+f"(d[0]), "+f"(d[1]), "+f"(d[2]), "+f"(d[3])
        : "r"(a[0]), "r"(a[1]), "r"(a[2]), "r"(a[3]), "r"(b0), "r"(b1));
}
__device__ __forceinline__ float ex2f(float x) {
    float r;
    asm("ex2.approx.ftz.f32 %0, %1;" : "=f"(r) : "f"(x));
    return r;
}
__device__ __forceinline__ unsigned packh2(float lo, float hi) {
    __half2 h2 = __floats2half2_rn(lo, hi);
    return *(unsigned*)&h2;
}
#define CP16(saddr, gptr) \
    asm volatile("cp.async.cg.shared.global [%0], [%1], 16;" :: "r"(saddr), "l"(gptr))
#define CP_COMMIT() asm volatile("cp.async.commit_group;" ::: "memory")
#define CP_WAIT0() asm volatile("cp.async.wait_group 0;" ::: "memory")
#define CP_WAIT1() asm volatile("cp.async.wait_group 1;" ::: "memory")

// ---------------- weight prep: transpose + fp16 hi/lo split ----------------
__global__ void wprep4(const float* __restrict__ W0, const float* __restrict__ W1,
                       const float* __restrict__ W2, const float* __restrict__ W3,
                       __half* __restrict__ Th, __half* __restrict__ Tl)
{
    __shared__ float tile[32][33];
    int z = blockIdx.z;
    const float* W = z == 0 ? W0 : z == 1 ? W1 : z == 2 ? W2 : W3;
    __half* th = Th + (size_t)z * H_ * H_;
    __half* tl = Tl + (size_t)z * H_ * H_;
    int k0 = blockIdx.x * 32, n0 = blockIdx.y * 32;
    int tx = threadIdx.x, ty = threadIdx.y;
    for (int i = ty; i < 32; i += 8)
        tile[i][tx] = W[(size_t)(k0 + i) * H_ + n0 + tx];
    __syncthreads();
    for (int i = ty; i < 32; i += 8) {
        float v = tile[tx][i];
        __half h = __float2half_rn(v);
        __half l = __float2half_rn(v - __half2float(h));
        size_t o = (size_t)(n0 + i) * H_ + k0 + tx;
        th[o] = h;
        tl[o] = l;
    }
}

// ---------------- elementwise fp16 convert (cross_states) ----------------
__global__ void conv16(const float* __restrict__ x, __half* __restrict__ o)
{
    int idx = (blockIdx.x * 256 + threadIdx.x) * 4;
    float4 v = *(const float4*)(x + idx);
    uint2 r;
    r.x = packh2(v.x, v.y);
    r.y = packh2(v.z, v.w);
    *(uint2*)(o + idx) = r;
}

// ---------------- mask int32 -> byte ----------------
__global__ void maskprep(const int* __restrict__ m, unsigned char* __restrict__ o)
{
    size_t i = ((size_t)blockIdx.x * 256 + threadIdx.x);
    const int4* mp = (const int4*)(m + i * 16);
    int4 a = mp[0], b = mp[1], c = mp[2], d = mp[3];
    uint4 r;
    r.x = (a.x!=0) | ((a.y!=0)<<8) | ((a.z!=0)<<16) | ((unsigned)(a.w!=0)<<24);
    r.y = (b.x!=0) | ((b.y!=0)<<8) | ((b.z!=0)<<16) | ((unsigned)(b.w!=0)<<24);
    r.z = (c.x!=0) | ((c.y!=0)<<8) | ((c.z!=0)<<16) | ((unsigned)(c.w!=0)<<24);
    r.w = (d.x!=0) | ((d.y!=0)<<8) | ((d.z!=0)<<16) | ((unsigned)(d.w!=0)<<24);
    *(uint4*)(o + i * 16) = r;
}

// ---------------- LayerNorm -> fp16 ----------------
__global__ void ln_kernel(const float* __restrict__ x, const float* __restrict__ gam,
                          const float* __restrict__ bet, __half* __restrict__ o)
{
    int row = blockIdx.x;
    int t = threadIdx.x;
    const float* xr = x + (size_t)row * H_;
    float v0 = xr[t], v1 = xr[t+256], v2 = xr[t+512];
    float s  = v0 + v1 + v2;
    float sq = v0*v0 + v1*v1 + v2*v2;
    #pragma unroll
    for (int off = 16; off; off >>= 1) {
        s  += __shfl_xor_sync(~0u, s,  off);
        sq += __shfl_xor_sync(~0u, sq, off);
    }
    __shared__ float rs[8], rq[8];
    int w = t >> 5;
    if ((t & 31) == 0) { rs[w] = s; rq[w] = sq; }
    __syncthreads();
    if (t < 32) {
        float a  = (t < 8) ? rs[t] : 0.f;
        float b2 = (t < 8) ? rq[t] : 0.f;
        #pragma unroll
        for (int off = 4; off; off >>= 1) {
            a  += __shfl_xor_sync(~0u, a,  off);
            b2 += __shfl_xor_sync(~0u, b2, off);
        }
        if (t == 0) { rs[0] = a; rq[0] = b2; }
    }
    __syncthreads();
    float mu  = rs[0] * (1.f / H_);
    float var = rq[0] * (1.f / H_) - mu * mu;
    float r   = rsqrtf(var + 1e-5f);
    __half* orow = o + (size_t)row * H_;
    #pragma unroll
    for (int e = 0; e < 3; e++) {
        int c = t + e * 256;
        float val = ((e==0?v0:e==1?v1:v2) - mu) * r * gam[c] + bet[c];
        orow[c] = __float2half_rn(val);
    }
}

// ---------------- GEMM: A fp16 x W fp16-hi/lo (2-term), cp.async 2-stage ----------------
#define GP2 40
#define GPLANE (128*GP2)
#define GSMEM (int)(2*3*GPLANE*sizeof(__half))   // 61440

__global__ void __launch_bounds__(256, 2) gemm_qkv(
    const __half* __restrict__ xn16, const __half* __restrict__ cr16,
    const __half* __restrict__ wth, const __half* __restrict__ wtl,
    const float* __restrict__ bq, const float* __restrict__ bk, const float* __restrict__ bv,
    const float* __restrict__ mem,
    const float* __restrict__ gate, const float* __restrict__ gbias,
    const float* __restrict__ dyn,
    __half* __restrict__ q16, __half* __restrict__ k16, __half* __restrict__ v16,
    float* __restrict__ Cf, int fused)
{
    extern __shared__ __half gsm[];
    int t = threadIdx.x, w = t >> 5, lane = t & 31;
    int wm = w & 1, wn = w >> 1;
    int m0 = blockIdx.x * 128, n0 = blockIdx.y * 128;
    int g = lane >> 2, qd = lane & 3;
    int z = blockIdx.z;

    const __half *A, *Bh, *Bl;
    const float *bias, *memadd = nullptr;
    __half *Co = nullptr;
    int mode;   // 0 plain, 1 +mem, 2 gate/dyn->float
    if (fused) {
        A = xn16; Bh = wth; Bl = wtl; bias = bq; mode = 2;
    } else if (z == 0) {
        A = xn16; Bh = wth; Bl = wtl; bias = bq; mode = 0; Co = q16;
    } else if (z == 1) {
        A = cr16; Bh = wth + (size_t)H_*H_; Bl = wtl + (size_t)H_*H_;
        bias = bk; mode = 1; memadd = mem; Co = k16;
    } else {
        A = cr16; Bh = wth + 2*(size_t)H_*H_; Bl = wtl + 2*(size_t)H_*H_;
        bias = bv; mode = 1; memadd = mem + (size_t)ROWS*H_; Co = v16;
    }

    auto load_stage = [&](int k0, int s) {
        #pragma unroll
        for (int p = 0; p < 3; p++) {
            const __half* src = p == 0 ? A : p == 1 ? Bh : Bl;
            int rbase = (p == 0) ? m0 : n0;
            __half* dst = gsm + (s*3 + p) * GPLANE;
            #pragma unroll
            for (int i = t; i < 512; i += 256) {
                int r = i >> 2, c = (i & 3) * 8;
                CP16(sa(dst + r*GP2 + c), src + (size_t)(rbase + r) * H_ + k0 + c);
            }
        }
        CP_COMMIT();
    };

    float acc[4][4][4] = {};
    int lr = lane & 15, lc = (lane >> 4) * 8;

    const unsigned aB0 = sa(gsm + 0*GPLANE + (wm*64 + lr)*GP2 + lc);
    const unsigned bH0 = sa(gsm + 1*GPLANE + (wn*32 + lr)*GP2 + lc);
    const unsigned bL0 = sa(gsm + 2*GPLANE + (wn*32 + lr)*GP2 + lc);
    const unsigned SOFF = 3*GPLANE*2;

    load_stage(0, 0);
    const int NIT = H_ / 32;
    for (int j = 0; j < NIT; j++) {
        int s = j & 1;
        if (j + 1 < NIT) { load_stage((j + 1) * 32, s ^ 1); CP_WAIT1(); }
        else             { CP_WAIT0(); }
        __syncthreads();

        unsigned so = s ? SOFF : 0;
        unsigned aB = aB0 + so, bH = bH0 + so, bL = bL0 + so;

        #pragma unroll
        for (int kh = 0; kh < 2; kh++) {
            unsigned a4[4][4], bh[2][4], bl[2][4];
            #pragma unroll
            for (int mt = 0; mt < 4; mt++)
                ldsm4(a4[mt], aB + (mt*16*GP2 + kh*16) * 2);
            #pragma unroll
            for (int ng = 0; ng < 2; ng++) {
                unsigned off = (ng*16*GP2 + kh*16) * 2;
                ldsm4(bh[ng], bH + off);
                ldsm4(bl[ng], bL + off);
            }
            #pragma unroll
            for (int mt = 0; mt < 4; mt++)
                #pragma unroll
                for (int ng = 0; ng < 2; ng++)
                    #pragma unroll
                    for (int tl = 0; tl < 2; tl++) {
                        float* d = acc[mt][ng*2 + tl];
                        mma_fp16(d, a4[mt], bh[ng][tl], bh[ng][tl+2]);
                        mma_fp16(d, a4[mt], bl[ng][tl], bl[ng][tl+2]);
                    }
        }
        __syncthreads();
    }

    float gv = 1.f, gb = 0.f;
    if (mode == 2) { gv = gate[0]; gb = gbias[0]; }
    #pragma unroll
    for (int mt = 0; mt < 4; mt++) {
        #pragma unroll
        for (int nt = 0; nt < 4; nt++) {
            int col = n0 + wn*32 + nt*8 + qd*2;
            float2 bvv = *(const float2*)(bias + col);
            #pragma unroll
            for (int rj = 0; rj < 2; rj++) {
                int row = m0 + wm*64 + mt*16 + g + rj*8;
                float x0 = acc[mt][nt][rj*2]   + bvv.x;
                float x1 = acc[mt][nt][rj*2+1] + bvv.y;
                if (mode == 1) {
                    float2 mm = *(const float2*)(memadd + (size_t)row * H_ + col);
                    x0 += 0.5f * mm.x; x1 += 0.5f * mm.y;
                }
                size_t o = (size_t)row * H_ + col;
                if (mode == 2) {
                    float d = dyn[row];
                    x0 = (x0*gv + gb) * d; x1 = (x1*gv + gb) * d;
                    *(float2*)(Cf + o) = make_float2(x0, x1);
                } else {
                    *(unsigned*)(Co + o) = packh2(x0, x1);
                }
            }
        }
    }
}

// ---------------- Flash attention: all fp16 single ----------------
#define FP 72
#define MPAD 80
#define NKT (S_/64)
// smem: Q | 2 stages x (K,V) | mask 2 x 64*MPAD
#define FSMEM (int)((1 + 2*2) * 64 * FP * 2 + 2 * 64 * MPAD)   // 56320

__global__ void __launch_bounds__(128) flash_mma(
    const __half* __restrict__ q16, const __half* __restrict__ k16,
    const __half* __restrict__ v16,
    const unsigned char* __restrict__ mask8,
    __half* __restrict__ ao16)
{
    extern __shared__ char fsm[];
    __half* Qs = (__half*)fsm;
    __half* KV = Qs + 64*FP;
    unsigned char* Ms = (unsigned char*)(KV + 2*2*64*FP);

    int t = threadIdx.x, w = t >> 5, lane = t & 31;
    int g = lane >> 2, qd = lane & 3;
    int q0 = blockIdx.x * 64, h = blockIdx.y, b = blockIdx.z;
    const size_t basec = (size_t)b * S_ * H_ + h * 64;
    const unsigned char* mb8 = mask8 + (size_t)b * S_ * S_;
    const float SCL = 0.125f * 1.44269504f;

    for (int i = t; i < 512; i += 128) {
        int r = i >> 3, c = (i & 7) * 8;
        *(uint4*)&Qs[r*FP + c] = *(const uint4*)(q16 + basec + (size_t)(q0 + r) * H_ + c);
    }

    auto load_stage = [&](int k0, int s) {
        #pragma unroll
        for (int p = 0; p < 2; p++) {
            const __half* src = p == 0 ? k16 : v16;
            __half* dst = KV + (s*2 + p) * 64*FP;
            #pragma unroll
            for (int i = t; i < 512; i += 128) {
                int r = i >> 3, c = (i & 7) * 8;
                CP16(sa(dst + r*FP + c), src + basec + (size_t)(k0 + r) * H_ + c);
            }
        }
        unsigned char* msp = Ms + s * 64*MPAD;
        #pragma unroll
        for (int i = t; i < 256; i += 128) {
            int r = i >> 2, c = (i & 3) * 16;
            CP16(sa(msp + r*MPAD + c), mb8 + (size_t)(q0 + r) * S_ + k0 + c);
        }
        CP_COMMIT();
    };

    load_stage(0, 0);
    __syncthreads();

    int lr = lane & 15, lc = (lane >> 4) * 8;
    unsigned qf[4][4];
    #pragma unroll
    for (int kb = 0; kb < 4; kb++)
        ldsm4(qf[kb], sa(&Qs[(w*16 + lr)*FP + lc + kb*16]));

    float mrow[2] = {-CUDART_INF_F, -CUDART_INF_F};
    float lrow_[2] = {0.f, 0.f};
    float oacc[8][4] = {};

    for (int j = 0; j < NKT; j++) {
        int s = j & 1;
        if (j + 1 < NKT) { load_stage((j + 1) * 64, s ^ 1); CP_WAIT1(); }
        else             { CP_WAIT0(); }
        __syncthreads();

        const __half* Ks = KV + (s*2 + 0) * 64*FP;
        const __half* Vs = KV + (s*2 + 1) * 64*FP;
        const unsigned char* msp = Ms + s * 64*MPAD;

        // S = Q K^T (1 mma per fragment pair)
        float sreg[8][4] = {};
        #pragma unroll
        for (int kb = 0; kb < 4; kb++) {
            #pragma unroll
            for (int ng = 0; ng < 4; ng++) {
                unsigned b4[4];
                ldsm4(b4, sa(Ks) + ((ng*16 + lr)*FP + lc + kb*16) * 2);
                #pragma unroll
                for (int tl = 0; tl < 2; tl++)
                    mma_fp16(sreg[ng*2 + tl], qf[kb], b4[tl], b4[tl+2]);
            }
        }

        // mask + scale (log2 domain)
        #pragma unroll
        for (int nt = 0; nt < 8; nt++)
            #pragma unroll
            for (int jj = 0; jj < 4; jj++) {
                int row = w*16 + g + (jj >> 1) * 8;
                int col = nt*8 + qd*2 + (jj & 1);
                sreg[nt][jj] = msp[row*MPAD + col] ? sreg[nt][jj] * SCL : -CUDART_INF_F;
            }

        // online softmax (base-2)
        #pragma unroll
        for (int rj = 0; rj < 2; rj++) {
            float mx = -CUDART_INF_F;
            #pragma unroll
            for (int nt = 0; nt < 8; nt++)
                mx = fmaxf(mx, fmaxf(sreg[nt][rj*2], sreg[nt][rj*2+1]));
            mx = fmaxf(mx, __shfl_xor_sync(~0u, mx, 1));
            mx = fmaxf(mx, __shfl_xor_sync(~0u, mx, 2));
            float nm = fmaxf(mrow[rj], mx);
            float corr, rsum = 0.f;
            if (nm == -CUDART_INF_F) {
                corr = 1.f;
                #pragma unroll
                for (int nt = 0; nt < 8; nt++) { sreg[nt][rj*2] = 0.f; sreg[nt][rj*2+1] = 0.f; }
            } else {
                corr = ex2f(mrow[rj] - nm);
                #pragma unroll
                for (int nt = 0; nt < 8; nt++) {
                    float p0 = ex2f(sreg[nt][rj*2]   - nm);
                    float p1 = ex2f(sreg[nt][rj*2+1] - nm);
                    sreg[nt][rj*2] = p0; sreg[nt][rj*2+1] = p1;
                    rsum += p0 + p1;
                }
            }
            rsum += __shfl_xor_sync(~0u, rsum, 1);
            rsum += __shfl_xor_sync(~0u, rsum, 2);
            mrow[rj] = nm;
            lrow_[rj] = lrow_[rj] * corr + rsum;
            #pragma unroll
            for (int nt = 0; nt < 8; nt++) {
                oacc[nt][rj*2]   *= corr;
                oacc[nt][rj*2+1] *= corr;
            }
        }

        // pack P -> fp16 A fragments
        unsigned pf[4][4];
        #pragma unroll
        for (int kb = 0; kb < 4; kb++) {
            #pragma unroll
            for (int half = 0; half < 2; half++) {
                int nt = kb*2 + half;
                pf[kb][half*2]   = packh2(sreg[nt][0], sreg[nt][1]);
                pf[kb][half*2+1] = packh2(sreg[nt][2], sreg[nt][3]);
            }
        }

        // O += P V
        #pragma unroll
        for (int kb = 0; kb < 4; kb++) {
            #pragma unroll
            for (int ng = 0; ng < 4; ng++) {
                unsigned v4[4];
                ldsm4t(v4, sa(Vs) + ((kb*16 + lr)*FP + ng*16 + lc) * 2);
                #pragma unroll
                for (int tl = 0; tl < 2; tl++)
                    mma_fp16(oacc[ng*2 + tl], pf[kb], v4[tl*2], v4[tl*2+1]);
            }
        }
        __syncthreads();
    }

    // epilogue -> fp16 single for out-proj GEMM
    #pragma unroll
    for (int rj = 0; rj < 2; rj++) {
        float inv = lrow_[rj] > 0.f ? 1.f / lrow_[rj] : 0.f;
        int row = q0 + w*16 + g + rj*8;
        #pragma unroll
        for (int nt = 0; nt < 8; nt++) {
            int col = nt*8 + qd*2;
            size_t o = basec + (size_t)row * H_ + col;
            *(unsigned*)(ao16 + o) = packh2(oacc[nt][rj*2] * inv, oacc[nt][rj*2+1] * inv);
        }
    }
}

// ---------------- launch ----------------
extern "C" void kernel_launch(void* const* d_in, const int* in_sizes, int n_in,
                              void* d_out, int out_size)
{
    const float* hidden = (const float*)d_in[0];
    const float* cross  = (const float*)d_in[1];
    const int*   amask  = (const int*)  d_in[2];
    const float* mem    = (const float*)d_in[3];
    const float* dyn    = (const float*)d_in[4];
    const float* Wq = (const float*)d_in[5];  const float* bq = (const float*)d_in[6];
    const float* Wk = (const float*)d_in[7];  const float* bk = (const float*)d_in[8];
    const float* Wv = (const float*)d_in[9];  const float* bv = (const float*)d_in[10];
    const float* Wo = (const float*)d_in[11]; const float* bo = (const float*)d_in[12];
    const float* gate  = (const float*)d_in[13];
    const float* gbias = (const float*)d_in[14];
    const float* lng   = (const float*)d_in[15];
    const float* lnb   = (const float*)d_in[16];
    float* out = (float*)d_out;

    __half *xn16,*cr16,*q16,*k16,*v16,*ao16,*wth,*wtl;
    unsigned char* m8;
    cudaGetSymbolAddress((void**)&xn16, g_xn16);
    cudaGetSymbolAddress((void**)&cr16, g_cr16);
    cudaGetSymbolAddress((void**)&q16,  g_q16);
    cudaGetSymbolAddress((void**)&k16,  g_k16);
    cudaGetSymbolAddress((void**)&v16,  g_v16);
    cudaGetSymbolAddress((void**)&ao16, g_ao16);
    cudaGetSymbolAddress((void**)&wth,  g_wt_hi);
    cudaGetSymbolAddress((void**)&wtl,  g_wt_lo);
    cudaGetSymbolAddress((void**)&m8,   g_mask8);

    cudaFuncSetAttribute(gemm_qkv, cudaFuncAttributeMaxDynamicSharedMemorySize, GSMEM);
    cudaFuncSetAttribute(flash_mma, cudaFuncAttributeMaxDynamicSharedMemorySize, FSMEM);

    wprep4<<<dim3(H_/32, H_/32, 4), dim3(32,8)>>>(Wq, Wk, Wv, Wo, wth, wtl);
    ln_kernel<<<ROWS, 256>>>(hidden, lng, lnb, xn16);
    conv16<<<ROWS*H_/1024, 256>>>(cross, cr16);
    maskprep<<<(size_t)B_*S_*S_/16/256, 256>>>(amask, m8);

    gemm_qkv<<<dim3(ROWS/128, H_/128, 3), 256, GSMEM>>>(
        xn16, cr16, wth, wtl, bq, bk, bv, mem,
        nullptr, nullptr, nullptr,
        q16, k16, v16, nullptr, 0);

    flash_mma<<<dim3(S_/64, NH_, B_), 128, FSMEM>>>(q16, k16, v16, m8, ao16);

    gemm_qkv<<<dim3(ROWS/128, H_/128, 1), 256, GSMEM>>>(
        ao16, nullptr, wth + 3*(size_t)H_*H_, wtl + 3*(size_t)H_*H_,
        bo, nullptr, nullptr, nullptr,
        gate, gbias, dyn,
        nullptr, nullptr, nullptr, out, 1);
}